// round 10
// baseline (speedup 1.0000x reference)
#include <cuda_runtime.h>
#include <cuda_bf16.h>
#include <math.h>

#define BATCH 256
#define S 200
#define D 192
#define NH 6
#define DH 32
#define NL 3
#define FF 576
#define RD 199
#define MTOT (BATCH*S)
#define XPAD 224

typedef __nv_bfloat16 bf16;

// ---------------- mma helpers -----------------------------------------------
__device__ __forceinline__ unsigned smem_u32(const void* p) {
    return (unsigned)__cvta_generic_to_shared(p);
}
__device__ __forceinline__ void ldsm_x4(unsigned addr, unsigned& r0, unsigned& r1,
                                        unsigned& r2, unsigned& r3) {
    asm volatile("ldmatrix.sync.aligned.m8n8.x4.shared.b16 {%0,%1,%2,%3}, [%4];"
                 : "=r"(r0), "=r"(r1), "=r"(r2), "=r"(r3) : "r"(addr));
}
__device__ __forceinline__ void ldsm_x4t(unsigned addr, unsigned& r0, unsigned& r1,
                                         unsigned& r2, unsigned& r3) {
    asm volatile("ldmatrix.sync.aligned.m8n8.x4.trans.shared.b16 {%0,%1,%2,%3}, [%4];"
                 : "=r"(r0), "=r"(r1), "=r"(r2), "=r"(r3) : "r"(addr));
}
__device__ __forceinline__ void mma16816(float c[4], const unsigned a[4], const unsigned b[2]) {
    asm volatile(
        "mma.sync.aligned.m16n8k16.row.col.f32.bf16.bf16.f32 "
        "{%0,%1,%2,%3}, {%4,%5,%6,%7}, {%8,%9}, {%0,%1,%2,%3};"
        : "+f"(c[0]), "+f"(c[1]), "+f"(c[2]), "+f"(c[3])
        : "r"(a[0]), "r"(a[1]), "r"(a[2]), "r"(a[3]), "r"(b[0]), "r"(b[1]));
}
__device__ __forceinline__ void split_bf(float x, bf16& h, bf16& l) {
    h = __float2bfloat16(x);
    l = __float2bfloat16(x - __bfloat162float(h));
}
__device__ __forceinline__ unsigned pack_bf2(bf16 a, bf16 b) {
    __nv_bfloat162 t(a, b);
    return *(unsigned*)&t;
}

// ---------------- scratch (device globals) ---------------------------------
__device__ float g_h[MTOT*D];
__device__ float g_raw[MTOT*D];
__device__ float g_q[MTOT*D];
__device__ float g_k[MTOT*D];
__device__ float g_v[MTOT*D];
__device__ float g_pool[BATCH*D];
__device__ float g_pooled[BATCH*D];

// bf16 hi/lo activation buffers
__device__ bf16 g_xh[200*BATCH*XPAD], g_xl[200*BATCH*XPAD];
__device__ bf16 g_hh[MTOT*D], g_hl[MTOT*D];
__device__ bf16 g_ah[MTOT*D], g_al[MTOT*D];
__device__ bf16 g_fh[MTOT*FF], g_fl[MTOT*FF];
// attention bf16 operand buffers
__device__ bf16 g_qbh[MTOT*D], g_qbl[MTOT*D];     // [bh][s][dh] (pre-scaled)
__device__ bf16 g_kth[MTOT*D], g_ktl[MTOT*D];     // [bh][dh][s]
__device__ bf16 g_vbh[MTOT*D], g_vbl[MTOT*D];     // [bh][s][dh]
// bf16 hi/lo weight buffers
__device__ bf16 g_rwh[200*RD*D], g_rwl[200*RD*D];
__device__ bf16 g_qkvh[NL*3*D*D], g_qkvl[NL*3*D*D];
__device__ bf16 g_woh[NL*D*D],   g_wol[NL*D*D];
__device__ bf16 g_w1h[NL*D*FF],  g_w1l[NL*D*FF];
__device__ bf16 g_w2h[NL*FF*D],  g_w2l[NL*FF*D];
__device__ bf16 g_pwh[3*D*D],    g_pwl[3*D*D];

__device__ __forceinline__ float gelu_exact(float x) {
    return 0.5f * x * (1.0f + erff(x * 0.70710678118654752f));
}

// ---------------- conversion kernels ----------------------------------------
__global__ void cvt_kernel(const float* __restrict__ in, bf16* __restrict__ hi,
                           bf16* __restrict__ lo, int n)
{
    int i = blockIdx.x * 256 + threadIdx.x;
    if (i < n) {
        bf16 h, l; split_bf(in[i], h, l);
        hi[i] = h; lo[i] = l;
    }
}

__global__ void cvt_x_kernel(const float* __restrict__ x,
                             bf16* __restrict__ hi, bf16* __restrict__ lo)
{
    int i = blockIdx.x * 256 + threadIdx.x;
    if (i >= 200 * BATCH * XPAD) return;
    int k = i % XPAD; int tmp = i / XPAD;
    int b = tmp % BATCH; int roi = tmp / BATCH;
    float v = (k < RD) ? x[(size_t)b * (200 * RD) + roi * RD + k] : 0.f;
    bf16 h, l; split_bf(v, h, l);
    hi[i] = h; lo[i] = l;
}

// ============================================================================
// Tensor-core GEMM, bf16x3, pre-split inputs, register-prefetch double buffer.
// BM=128, BN=64, BK=32, 256 thr.
// mode 0: QKV fp32 scatter (pool); mode 1: FFN1 (+GELU) -> bf16 pair;
// mode 2: tokenizer; mode 3: raw fp32 C; mode 4: QKV bf16 scatter + K^T.
// ============================================================================
__global__ __launch_bounds__(256) void mma_gemm_kernel(
    const bf16* __restrict__ Ah, const bf16* __restrict__ Al,
    const bf16* __restrict__ Wh, const bf16* __restrict__ Wl,
    const float* __restrict__ bias,
    float* __restrict__ oq, float* __restrict__ ok, float* __restrict__ ov,
    float* __restrict__ of, bf16* __restrict__ obh, bf16* __restrict__ obl,
    bf16* __restrict__ xqh, bf16* __restrict__ xql,
    bf16* __restrict__ xkh, bf16* __restrict__ xkl,
    bf16* __restrict__ xvh, bf16* __restrict__ xvl,
    int mode, int K, int lda)
{
    __shared__ bf16 AsH[128][40];
    __shared__ bf16 AsL[128][40];
    __shared__ bf16 BsH[32][72];
    __shared__ bf16 BsL[32][72];

    int m0 = blockIdx.x * 128, n0 = blockIdx.y * 64, roi = blockIdx.z;
    int t = threadIdx.x;
    int warp = t >> 5, lane = t & 31;
    int wm = warp >> 1, wn = warp & 1;

    const bf16 *Bph, *Bpl; int ldb, nb;
    if (mode == 0 || mode == 4) {
        int wh = n0 / D;
        Bph = Wh + (size_t)wh * D * D; Bpl = Wl + (size_t)wh * D * D;
        nb = n0 - wh * D; ldb = D;
    } else if (mode == 1) { Bph = Wh; Bpl = Wl; nb = n0; ldb = FF; }
    else if (mode == 2) { Bph = Wh + (size_t)roi * RD * D; Bpl = Wl + (size_t)roi * RD * D; nb = n0; ldb = D; }
    else                { Bph = Wh; Bpl = Wl; nb = n0; ldb = D; }

    if (mode == 2) {
        Ah += (size_t)roi * BATCH * XPAD;
        Al += (size_t)roi * BATCH * XPAD;
    }

    float acc[2][4][4] = {};

    // ---- preload tile 0 ----
#pragma unroll
    for (int p = t; p < 1024; p += 256) {
        int row = p >> 3, c4 = (p & 7) * 4;
        size_t off = (size_t)(m0 + row) * lda + c4;
        *(uint2*)&AsH[row][c4] = *(const uint2*)(Ah + off);
        *(uint2*)&AsL[row][c4] = *(const uint2*)(Al + off);
    }
#pragma unroll
    for (int p = t; p < 512; p += 256) {
        int k = p >> 4, n4 = (p & 15) * 4;
        uint2 zh = make_uint2(0u, 0u), zl = make_uint2(0u, 0u);
        if (k < K) {
            size_t off = (size_t)k * ldb + nb + n4;
            zh = *(const uint2*)(Bph + off);
            zl = *(const uint2*)(Bpl + off);
        }
        *(uint2*)&BsH[k][n4] = zh;
        *(uint2*)&BsL[k][n4] = zl;
    }
    __syncthreads();

    for (int k0 = 0; k0 < K; k0 += 32) {
        bool has_next = (k0 + 32 < K);
        uint2 pa[4][2], pb[2][2];
        if (has_next) {
            int kn = k0 + 32;
#pragma unroll
            for (int i = 0; i < 4; ++i) {
                int p = t + i * 256;
                int row = p >> 3, c4 = (p & 7) * 4;
                size_t off = (size_t)(m0 + row) * lda + kn + c4;
                pa[i][0] = *(const uint2*)(Ah + off);
                pa[i][1] = *(const uint2*)(Al + off);
            }
#pragma unroll
            for (int i = 0; i < 2; ++i) {
                int p = t + i * 256;
                int k = p >> 4, n4 = (p & 15) * 4;
                uint2 zh = make_uint2(0u, 0u), zl = make_uint2(0u, 0u);
                if (kn + k < K) {
                    size_t off = (size_t)(kn + k) * ldb + nb + n4;
                    zh = *(const uint2*)(Bph + off);
                    zl = *(const uint2*)(Bpl + off);
                }
                pb[i][0] = zh; pb[i][1] = zl;
            }
        }

#pragma unroll
        for (int ks = 0; ks < 2; ++ks) {
            int kb = ks * 16;
            unsigned aH[2][4], aL[2][4];
            int aro = ((lane >> 3) & 1) * 8 + (lane & 7);
            int aco = kb + (lane >> 4) * 8;
#pragma unroll
            for (int mt = 0; mt < 2; ++mt) {
                int r = wm * 32 + mt * 16 + aro;
                ldsm_x4(smem_u32(&AsH[r][aco]), aH[mt][0], aH[mt][1], aH[mt][2], aH[mt][3]);
                ldsm_x4(smem_u32(&AsL[r][aco]), aL[mt][0], aL[mt][1], aL[mt][2], aL[mt][3]);
            }
            unsigned bH[4][2], bL[4][2];
            int bro = kb + ((lane >> 3) & 1) * 8 + (lane & 7);
            int bco = wn * 32 + (lane >> 4) * 8;
#pragma unroll
            for (int np = 0; np < 2; ++np) {
                unsigned r0, r1, r2, r3;
                ldsm_x4t(smem_u32(&BsH[bro][bco + np * 16]), r0, r1, r2, r3);
                bH[np*2][0] = r0; bH[np*2][1] = r1; bH[np*2+1][0] = r2; bH[np*2+1][1] = r3;
                ldsm_x4t(smem_u32(&BsL[bro][bco + np * 16]), r0, r1, r2, r3);
                bL[np*2][0] = r0; bL[np*2][1] = r1; bL[np*2+1][0] = r2; bL[np*2+1][1] = r3;
            }
#pragma unroll
            for (int mt = 0; mt < 2; ++mt)
#pragma unroll
                for (int nt = 0; nt < 4; ++nt) {
                    mma16816(acc[mt][nt], aH[mt], bH[nt]);
                    mma16816(acc[mt][nt], aH[mt], bL[nt]);
                    mma16816(acc[mt][nt], aL[mt], bH[nt]);
                }
        }

        if (has_next) {
            __syncthreads();
#pragma unroll
            for (int i = 0; i < 4; ++i) {
                int p = t + i * 256;
                int row = p >> 3, c4 = (p & 7) * 4;
                *(uint2*)&AsH[row][c4] = pa[i][0];
                *(uint2*)&AsL[row][c4] = pa[i][1];
            }
#pragma unroll
            for (int i = 0; i < 2; ++i) {
                int p = t + i * 256;
                int k = p >> 4, n4 = (p & 15) * 4;
                *(uint2*)&BsH[k][n4] = pb[i][0];
                *(uint2*)&BsL[k][n4] = pb[i][1];
            }
            __syncthreads();
        }
    }

    // ---- epilogue ----
    int g = lane >> 2, tq = (lane & 3) * 2;
#pragma unroll
    for (int mt = 0; mt < 2; ++mt) {
        int r0 = m0 + wm * 32 + mt * 16 + g;
#pragma unroll
        for (int nt = 0; nt < 4; ++nt) {
            float* c = acc[mt][nt];
            if (mode == 0) {
                int wh = n0 / D;
                int colq = nb + wn * 32 + nt * 8 + tq;
                int hd = colq >> 5, dh = colq & 31;
                float2 bb = *(const float2*)(bias + wh * D + colq);
                float* o = (wh == 0) ? oq : ((wh == 1) ? ok : ov);
                int m = r0;
                int b = m / S, s = m - b * S;
                *(float2*)(o + (((size_t)b * NH + hd) * S + s) * DH + dh)
                    = make_float2(c[0] + bb.x, c[1] + bb.y);
                m = r0 + 8; b = m / S; s = m - b * S;
                *(float2*)(o + (((size_t)b * NH + hd) * S + s) * DH + dh)
                    = make_float2(c[2] + bb.x, c[3] + bb.y);
            } else if (mode == 4) {
                int wh = n0 / D;
                int colq = nb + wn * 32 + nt * 8 + tq;
                int hd = colq >> 5, dh = colq & 31;
                float2 bb = *(const float2*)(bias + wh * D + colq);
#pragma unroll
                for (int rr = 0; rr < 2; ++rr) {
                    int m = r0 + rr * 8;
                    int b = m / S, s = m - b * S;
                    int bhq = b * NH + hd;
                    float f0 = c[rr * 2 + 0] + bb.x;
                    float f1 = c[rr * 2 + 1] + bb.y;
                    bf16 h0, l0, h1, l1;
                    if (wh == 0) {
                        f0 *= 0.17677669529663687f; f1 *= 0.17677669529663687f;
                        split_bf(f0, h0, l0); split_bf(f1, h1, l1);
                        size_t off = ((size_t)bhq * S + s) * DH + dh;
                        *(__nv_bfloat162*)(xqh + off) = __nv_bfloat162(h0, h1);
                        *(__nv_bfloat162*)(xql + off) = __nv_bfloat162(l0, l1);
                    } else if (wh == 1) {
                        split_bf(f0, h0, l0); split_bf(f1, h1, l1);
                        size_t off = ((size_t)bhq * DH + dh) * S + s;
                        xkh[off] = h0; xkh[off + S] = h1;
                        xkl[off] = l0; xkl[off + S] = l1;
                    } else {
                        split_bf(f0, h0, l0); split_bf(f1, h1, l1);
                        size_t off = ((size_t)bhq * S + s) * DH + dh;
                        *(__nv_bfloat162*)(xvh + off) = __nv_bfloat162(h0, h1);
                        *(__nv_bfloat162*)(xvl + off) = __nv_bfloat162(l0, l1);
                    }
                }
            } else if (mode == 1) {
                int col = n0 + wn * 32 + nt * 8 + tq;
                float2 bb = *(const float2*)(bias + col);
                float f0 = gelu_exact(c[0] + bb.x), f1 = gelu_exact(c[1] + bb.y);
                bf16 h0, l0, h1, l1;
                split_bf(f0, h0, l0); split_bf(f1, h1, l1);
                *(__nv_bfloat162*)(obh + (size_t)r0 * FF + col) = __nv_bfloat162(h0, h1);
                *(__nv_bfloat162*)(obl + (size_t)r0 * FF + col) = __nv_bfloat162(l0, l1);
                f0 = gelu_exact(c[2] + bb.x); f1 = gelu_exact(c[3] + bb.y);
                split_bf(f0, h0, l0); split_bf(f1, h1, l1);
                *(__nv_bfloat162*)(obh + (size_t)(r0 + 8) * FF + col) = __nv_bfloat162(h0, h1);
                *(__nv_bfloat162*)(obl + (size_t)(r0 + 8) * FF + col) = __nv_bfloat162(l0, l1);
            } else if (mode == 2) {
                int col = n0 + wn * 32 + nt * 8 + tq;
                float2 bb = *(const float2*)(bias + (size_t)roi * D + col);
                *(float2*)(of + ((size_t)r0 * S + roi) * D + col)
                    = make_float2(c[0] + bb.x, c[1] + bb.y);
                *(float2*)(of + ((size_t)(r0 + 8) * S + roi) * D + col)
                    = make_float2(c[2] + bb.x, c[3] + bb.y);
            } else {
                int col = n0 + wn * 32 + nt * 8 + tq;
                float2 bb = *(const float2*)(bias + col);
                *(float2*)(of + (size_t)r0 * D + col)
                    = make_float2(c[0] + bb.x, c[1] + bb.y);
                *(float2*)(of + (size_t)(r0 + 8) * D + col)
                    = make_float2(c[2] + bb.x, c[3] + bb.y);
            }
        }
    }
}

// ============================================================================
// Tensor-core attention with register-prefetch K/V double buffer.
// CTA per (b,h), 8 warps, queries padded to 208, keys in 32-key tiles.
// ============================================================================
__global__ __launch_bounds__(256, 2) void attn_mma_kernel(
    const bf16* __restrict__ qbh, const bf16* __restrict__ qbl,
    const bf16* __restrict__ kth, const bf16* __restrict__ ktl,
    const bf16* __restrict__ vbh, const bf16* __restrict__ vbl,
    bf16* __restrict__ oh, bf16* __restrict__ ol)
{
    __shared__ bf16 Qh[208][40], Ql[208][40];
    __shared__ bf16 Kh[32][40],  Kl[32][40];
    __shared__ bf16 Vh[32][40],  Vl[32][40];

    int bh = blockIdx.x;
    int b = bh / NH, hd = bh - b * NH;
    int t = threadIdx.x, warp = t >> 5, lane = t & 31;
    int g = lane >> 2, tq = lane & 3;

    const bf16* khb = kth + (size_t)bh * DH * S;
    const bf16* klb = ktl + (size_t)bh * DH * S;
    const unsigned* vhp = (const unsigned*)(vbh + (size_t)bh * S * DH);
    const unsigned* vlp = (const unsigned*)(vbl + (size_t)bh * S * DH);

    // load Q (zero-padded rows 200..207)
    const unsigned* qhp = (const unsigned*)(qbh + (size_t)bh * S * DH);
    const unsigned* qlp = (const unsigned*)(qbl + (size_t)bh * S * DH);
    for (int i = t; i < 208 * 16; i += 256) {
        int row = i >> 4, cp = i & 15;
        unsigned a = 0, c = 0;
        if (row < S) { a = qhp[row * 16 + cp]; c = qlp[row * 16 + cp]; }
        *(unsigned*)&Qh[row][cp * 2] = a;
        *(unsigned*)&Ql[row][cp * 2] = c;
    }
    // load K/V tile 0
#pragma unroll
    for (int i = t; i < 512; i += 256) {
        int row = i >> 4, cp = i & 15;
        int key = cp * 2;
        *(unsigned*)&Kh[row][cp * 2] = *(const unsigned*)(khb + row * S + key);
        *(unsigned*)&Kl[row][cp * 2] = *(const unsigned*)(klb + row * S + key);
        int keyv = row;
        *(unsigned*)&Vh[row][cp * 2] = vhp[keyv * 16 + cp];
        *(unsigned*)&Vl[row][cp * 2] = vlp[keyv * 16 + cp];
    }
    __syncthreads();

    int nmt = (warp < 5) ? 2 : 1;
    int mt0 = warp * 16, mt1 = (8 + warp) * 16;

    int aro  = ((lane >> 3) & 1) * 8 + (lane & 7);
    int acoh = (lane >> 4) * 8;

    // hoist Q fragments (loop-invariant over key tiles)
    unsigned qH[2][2][4], qL[2][2][4];
    for (int mi = 0; mi < nmt; ++mi) {
        int mrow = mi ? mt1 : mt0;
#pragma unroll
        for (int ks = 0; ks < 2; ++ks) {
            ldsm_x4(smem_u32(&Qh[mrow + aro][ks * 16 + acoh]),
                    qH[mi][ks][0], qH[mi][ks][1], qH[mi][ks][2], qH[mi][ks][3]);
            ldsm_x4(smem_u32(&Ql[mrow + aro][ks * 16 + acoh]),
                    qL[mi][ks][0], qL[mi][ks][1], qL[mi][ks][2], qL[mi][ks][3]);
        }
    }

    float oacc[2][4][4] = {};
    float lsum[2][2] = {};

    for (int kt = 0; kt < 7; ++kt) {
        bool has_next = (kt < 6);
        unsigned pk[2][2], pv[2][2];
        if (has_next) {
            int kn0 = (kt + 1) * 32;
#pragma unroll
            for (int i = 0; i < 2; ++i) {
                int p = t + i * 256;
                int row = p >> 4, cp = p & 15;
                int key = kn0 + cp * 2;
                unsigned a = 0, c = 0;
                if (key < S) {
                    a = *(const unsigned*)(khb + row * S + key);
                    c = *(const unsigned*)(klb + row * S + key);
                }
                pk[i][0] = a; pk[i][1] = c;
                int keyv = kn0 + row;
                unsigned av = 0, cv = 0;
                if (keyv < S) { av = vhp[keyv * 16 + cp]; cv = vlp[keyv * 16 + cp]; }
                pv[i][0] = av; pv[i][1] = cv;
            }
        }

        int kt0 = kt * 32;
        for (int mi = 0; mi < nmt; ++mi) {
#pragma unroll
            for (int kg = 0; kg < 2; ++kg) {
                float sc2[2][4] = {};
#pragma unroll
                for (int ks = 0; ks < 2; ++ks) {
                    unsigned kh2[2][2], kl2[2][2], r0, r1, r2, r3;
                    ldsm_x4t(smem_u32(&Kh[ks * 16 + aro][kg * 16 + acoh]), r0, r1, r2, r3);
                    kh2[0][0] = r0; kh2[0][1] = r1; kh2[1][0] = r2; kh2[1][1] = r3;
                    ldsm_x4t(smem_u32(&Kl[ks * 16 + aro][kg * 16 + acoh]), r0, r1, r2, r3);
                    kl2[0][0] = r0; kl2[0][1] = r1; kl2[1][0] = r2; kl2[1][1] = r3;
#pragma unroll
                    for (int j = 0; j < 2; ++j) {
                        mma16816(sc2[j], qH[mi][ks], kh2[j]);
                        mma16816(sc2[j], qH[mi][ks], kl2[j]);
                        mma16816(sc2[j], qL[mi][ks], kh2[j]);
                    }
                }
                float e[8];
#pragma unroll
                for (int j = 0; j < 2; ++j) {
                    int keyb = kt0 + (kg * 2 + j) * 8 + tq * 2;
                    float e0 = __expf(sc2[j][0]);
                    float e1 = __expf(sc2[j][1]);
                    float e2 = __expf(sc2[j][2]);
                    float e3 = __expf(sc2[j][3]);
                    if (keyb >= S)     { e0 = 0.f; e2 = 0.f; }
                    if (keyb + 1 >= S) { e1 = 0.f; e3 = 0.f; }
                    lsum[mi][0] += e0 + e1;
                    lsum[mi][1] += e2 + e3;
                    e[j * 4 + 0] = e0; e[j * 4 + 1] = e1;
                    e[j * 4 + 2] = e2; e[j * 4 + 3] = e3;
                }
                unsigned paH[4], paL[4];
                {
                    bf16 h0, l0, h1, l1;
                    split_bf(e[0], h0, l0); split_bf(e[1], h1, l1);
                    paH[0] = pack_bf2(h0, h1); paL[0] = pack_bf2(l0, l1);
                    split_bf(e[2], h0, l0); split_bf(e[3], h1, l1);
                    paH[1] = pack_bf2(h0, h1); paL[1] = pack_bf2(l0, l1);
                    split_bf(e[4], h0, l0); split_bf(e[5], h1, l1);
                    paH[2] = pack_bf2(h0, h1); paL[2] = pack_bf2(l0, l1);
                    split_bf(e[6], h0, l0); split_bf(e[7], h1, l1);
                    paH[3] = pack_bf2(h0, h1); paL[3] = pack_bf2(l0, l1);
                }
#pragma unroll
                for (int np = 0; np < 2; ++np) {
                    unsigned vh2[2][2], vl2[2][2], r0, r1, r2, r3;
                    ldsm_x4t(smem_u32(&Vh[kg * 16 + aro][np * 16 + acoh]), r0, r1, r2, r3);
                    vh2[0][0] = r0; vh2[0][1] = r1; vh2[1][0] = r2; vh2[1][1] = r3;
                    ldsm_x4t(smem_u32(&Vl[kg * 16 + aro][np * 16 + acoh]), r0, r1, r2, r3);
                    vl2[0][0] = r0; vl2[0][1] = r1; vl2[1][0] = r2; vl2[1][1] = r3;
#pragma unroll
                    for (int j = 0; j < 2; ++j) {
                        int n8 = np * 2 + j;
                        mma16816(oacc[mi][n8], paH, vh2[j]);
                        mma16816(oacc[mi][n8], paH, vl2[j]);
                        mma16816(oacc[mi][n8], paL, vh2[j]);
                    }
                }
            }
        }

        if (has_next) {
            __syncthreads();
#pragma unroll
            for (int i = 0; i < 2; ++i) {
                int p = t + i * 256;
                int row = p >> 4, cp = p & 15;
                *(unsigned*)&Kh[row][cp * 2] = pk[i][0];
                *(unsigned*)&Kl[row][cp * 2] = pk[i][1];
                *(unsigned*)&Vh[row][cp * 2] = pv[i][0];
                *(unsigned*)&Vl[row][cp * 2] = pv[i][1];
            }
            __syncthreads();
        }
    }

    // finalize: reduce l over quad, scale, store bf16 hi/lo
    for (int mi = 0; mi < nmt; ++mi) {
        float l0 = lsum[mi][0], l1 = lsum[mi][1];
        l0 += __shfl_xor_sync(0xffffffffu, l0, 1);
        l0 += __shfl_xor_sync(0xffffffffu, l0, 2);
        l1 += __shfl_xor_sync(0xffffffffu, l1, 1);
        l1 += __shfl_xor_sync(0xffffffffu, l1, 2);
        float i0 = 1.f / l0, i1 = 1.f / l1;
        int mrow = mi ? mt1 : mt0;
        int s0 = mrow + g;
#pragma unroll
        for (int n8 = 0; n8 < 4; ++n8) {
            int col = hd * DH + n8 * 8 + tq * 2;
            if (s0 < S) {
                float f0 = oacc[mi][n8][0] * i0, f1 = oacc[mi][n8][1] * i0;
                bf16 h0, lo0, h1, lo1;
                split_bf(f0, h0, lo0); split_bf(f1, h1, lo1);
                size_t off = ((size_t)b * S + s0) * D + col;
                *(__nv_bfloat162*)(oh + off) = __nv_bfloat162(h0, h1);
                *(__nv_bfloat162*)(ol + off) = __nv_bfloat162(lo0, lo1);
            }
            if (s0 + 8 < S) {
                float f0 = oacc[mi][n8][2] * i1, f1 = oacc[mi][n8][3] * i1;
                bf16 h0, lo0, h1, lo1;
                split_bf(f0, h0, lo0); split_bf(f1, h1, lo1);
                size_t off = ((size_t)b * S + s0 + 8) * D + col;
                *(__nv_bfloat162*)(oh + off) = __nv_bfloat162(h0, h1);
                *(__nv_bfloat162*)(ol + off) = __nv_bfloat162(lo0, lo1);
            }
        }
    }
}

// ============================================================================
// add + LayerNorm: out = LN(raw + res) -> fp32 h + bf16 hi/lo
// ============================================================================
__global__ void addln_kernel(const float* __restrict__ raw,
                             const float* __restrict__ res,
                             const float* __restrict__ lng,
                             const float* __restrict__ lnb,
                             float* __restrict__ out,
                             bf16* __restrict__ oh, bf16* __restrict__ ol)
{
    int row = blockIdx.x * 8 + (threadIdx.x >> 5);
    int lane = threadIdx.x & 31;
    float vv[6];
    float sum = 0.f, sq = 0.f;
#pragma unroll
    for (int j = 0; j < 6; ++j) {
        int c = lane + 32 * j;
        vv[j] = raw[(size_t)row * D + c] + res[(size_t)row * D + c];
        sum += vv[j]; sq += vv[j] * vv[j];
    }
#pragma unroll
    for (int o = 16; o > 0; o >>= 1) {
        sum += __shfl_xor_sync(0xffffffffu, sum, o);
        sq  += __shfl_xor_sync(0xffffffffu, sq,  o);
    }
    float mean = sum * (1.f / D);
    float rstd = rsqrtf(sq * (1.f / D) - mean * mean + 1e-5f);
#pragma unroll
    for (int j = 0; j < 6; ++j) {
        int c = lane + 32 * j;
        float val = (vv[j] - mean) * rstd * lng[c] + lnb[c];
        out[(size_t)row * D + c] = val;
        bf16 h, l; split_bf(val, h, l);
        oh[(size_t)row * D + c] = h; ol[(size_t)row * D + c] = l;
    }
}

// ============================================================================
// token epilogue: per-roi LN + GELU + pos -> fp32 h + bf16 hi/lo
// ============================================================================
__global__ void tok_finish_kernel(const float* __restrict__ raw,
                                  const float* __restrict__ lng,
                                  const float* __restrict__ lnb,
                                  const float* __restrict__ pos,
                                  float* __restrict__ out,
                                  bf16* __restrict__ oh, bf16* __restrict__ ol)
{
    int row = blockIdx.x * 8 + (threadIdx.x >> 5);
    int roi = row % S;
    int lane = threadIdx.x & 31;
    float vv[6];
    float sum = 0.f, sq = 0.f;
#pragma unroll
    for (int j = 0; j < 6; ++j) {
        vv[j] = raw[(size_t)row * D + lane + 32 * j];
        sum += vv[j]; sq += vv[j] * vv[j];
    }
#pragma unroll
    for (int o = 16; o > 0; o >>= 1) {
        sum += __shfl_xor_sync(0xffffffffu, sum, o);
        sq  += __shfl_xor_sync(0xffffffffu, sq,  o);
    }
    float mean = sum * (1.f / D);
    float rstd = rsqrtf(sq * (1.f / D) - mean * mean + 1e-5f);
#pragma unroll
    for (int j = 0; j < 6; ++j) {
        int c = lane + 32 * j;
        float v = (vv[j] - mean) * rstd * lng[(size_t)roi * D + c] + lnb[(size_t)roi * D + c];
        float val = gelu_exact(v) + pos[(size_t)roi * D + c];
        out[(size_t)row * D + c] = val;
        bf16 h, l; split_bf(val, h, l);
        oh[(size_t)row * D + c] = h; ol[(size_t)row * D + c] = l;
    }
}

// ---------------- pooled attention (Q=1 via linearity) ---------------------
__global__ void pool_attn_kernel(const float* __restrict__ q,
                                 const float* __restrict__ k,
                                 const float* __restrict__ v,
                                 float* __restrict__ out)
{
    __shared__ float qm[DH];
    __shared__ float sc[S];
    __shared__ float red[2];
    int bh = blockIdx.x;
    int b = bh / NH, hd = bh % NH;
    size_t base = (size_t)bh * S * DH;
    int t = threadIdx.x;
    if (t < DH) {
        float s = 0.f;
        for (int j = 0; j < S; ++j) s += q[base + j * DH + t];
        qm[t] = s * (1.f / S) * 0.17677669529663687f;
    }
    __syncthreads();
    if (t < S) {
        float x = 0.f;
#pragma unroll
        for (int i = 0; i < DH; ++i) x += qm[i] * k[base + t * DH + i];
        sc[t] = x;
    }
    __syncthreads();
    if (t == 0) {
        float mx = -1e30f;
        for (int s = 0; s < S; ++s) mx = fmaxf(mx, sc[s]);
        red[0] = mx;
    }
    __syncthreads();
    if (t < S) sc[t] = __expf(sc[t] - red[0]);
    __syncthreads();
    if (t == 0) {
        float l = 0.f;
        for (int s = 0; s < S; ++s) l += sc[s];
        red[1] = 1.f / l;
    }
    __syncthreads();
    if (t < DH) {
        float o = 0.f;
        for (int s = 0; s < S; ++s) o += sc[s] * v[base + s * DH + t];
        out[(size_t)b * D + hd * DH + t] = o * red[1];
    }
}

// ---------------- pooled projection ----------------------------------------
__global__ void pool_proj_kernel(const float* __restrict__ in,
                                 const float* __restrict__ W,
                                 const float* __restrict__ bias,
                                 float* __restrict__ out)
{
    __shared__ float row[D];
    int b = blockIdx.x, d = threadIdx.x;
    row[d] = in[(size_t)b * D + d];
    __syncthreads();
    float s = bias[d];
    for (int k = 0; k < D; ++k) s += row[k] * W[(size_t)k * D + d];
    out[(size_t)b * D + d] = s;
}

// ---------------- classifier head ------------------------------------------
__global__ void cls_kernel(const float* __restrict__ in,
                           const float* __restrict__ g,  const float* __restrict__ bt,
                           const float* __restrict__ W1, const float* __restrict__ b1,
                           const float* __restrict__ W2, const float* __restrict__ b2,
                           const float* __restrict__ W3, const float* __restrict__ b3,
                           float* __restrict__ out)
{
    __shared__ float z[D];
    __shared__ float z1[96];
    __shared__ float z2[48];
    __shared__ float red[2];
    int b = blockIdx.x, t = threadIdx.x;
    float v = in[(size_t)b * D + t];
    z[t] = v;
    __syncthreads();
    if (t == 0) {
        float s = 0.f, sq = 0.f;
        for (int i = 0; i < D; ++i) { s += z[i]; sq += z[i] * z[i]; }
        float m = s / D;
        red[0] = m;
        red[1] = rsqrtf(sq / D - m * m + 1e-5f);
    }
    __syncthreads();
    z[t] = (v - red[0]) * red[1] * g[t] + bt[t];
    __syncthreads();
    if (t < 96) {
        float a = b1[t];
        for (int k = 0; k < D; ++k) a += z[k] * W1[k * 96 + t];
        z1[t] = gelu_exact(a);
    }
    __syncthreads();
    if (t < 48) {
        float a = b2[t];
        for (int k = 0; k < 96; ++k) a += z1[k] * W2[k * 48 + t];
        z2[t] = gelu_exact(a);
    }
    __syncthreads();
    if (t < 2) {
        float a = b3[t];
        for (int k = 0; k < 48; ++k) a += z2[k] * W3[k * 2 + t];
        out[(size_t)b * 2 + t] = a;
    }
}

// ---------------- launch ----------------------------------------------------
extern "C" void kernel_launch(void* const* d_in, const int* in_sizes, int n_in,
                              void* d_out, int out_size)
{
    const float* x        = (const float*)d_in[0];
    const float* roi_W    = (const float*)d_in[1];
    const float* roi_b    = (const float*)d_in[2];
    const float* roi_lng  = (const float*)d_in[3];
    const float* roi_lnb  = (const float*)d_in[4];
    const float* pos_emb  = (const float*)d_in[5];
    const float* enc_Wqkv = (const float*)d_in[6];
    const float* enc_bqkv = (const float*)d_in[7];
    const float* enc_Wo   = (const float*)d_in[8];
    const float* enc_bo   = (const float*)d_in[9];
    const float* enc_ln1g = (const float*)d_in[10];
    const float* enc_ln1b = (const float*)d_in[11];
    const float* enc_W1   = (const float*)d_in[12];
    const float* enc_b1   = (const float*)d_in[13];
    const float* enc_W2   = (const float*)d_in[14];
    const float* enc_b2   = (const float*)d_in[15];
    const float* enc_ln2g = (const float*)d_in[16];
    const float* enc_ln2b = (const float*)d_in[17];
    const float* pool_Wqkv= (const float*)d_in[18];
    const float* pool_bqkv= (const float*)d_in[19];
    const float* pool_Wo  = (const float*)d_in[20];
    const float* pool_bo  = (const float*)d_in[21];
    const float* cls_lng  = (const float*)d_in[22];
    const float* cls_lnb  = (const float*)d_in[23];
    const float* cls_W1   = (const float*)d_in[24];
    const float* cls_b1   = (const float*)d_in[25];
    const float* cls_W2   = (const float*)d_in[26];
    const float* cls_b2   = (const float*)d_in[27];
    const float* cls_W3   = (const float*)d_in[28];
    const float* cls_b3   = (const float*)d_in[29];
    float* out = (float*)d_out;

    float *h, *raw, *q, *k, *v, *pool, *pooled;
    bf16 *xh, *xl, *hh, *hl, *ah, *al, *fh, *fl;
    bf16 *qbh, *qbl, *kth, *ktl, *vbh, *vbl;
    bf16 *rwh, *rwl, *qkvh, *qkvl, *woh, *wol, *w1h, *w1l, *w2h, *w2l, *pwh, *pwl;
    cudaGetSymbolAddress((void**)&h,    g_h);
    cudaGetSymbolAddress((void**)&raw,  g_raw);
    cudaGetSymbolAddress((void**)&q,    g_q);
    cudaGetSymbolAddress((void**)&k,    g_k);
    cudaGetSymbolAddress((void**)&v,    g_v);
    cudaGetSymbolAddress((void**)&pool, g_pool);
    cudaGetSymbolAddress((void**)&pooled, g_pooled);
    cudaGetSymbolAddress((void**)&xh, g_xh);   cudaGetSymbolAddress((void**)&xl, g_xl);
    cudaGetSymbolAddress((void**)&hh, g_hh);   cudaGetSymbolAddress((void**)&hl, g_hl);
    cudaGetSymbolAddress((void**)&ah, g_ah);   cudaGetSymbolAddress((void**)&al, g_al);
    cudaGetSymbolAddress((void**)&fh, g_fh);   cudaGetSymbolAddress((void**)&fl, g_fl);
    cudaGetSymbolAddress((void**)&qbh, g_qbh); cudaGetSymbolAddress((void**)&qbl, g_qbl);
    cudaGetSymbolAddress((void**)&kth, g_kth); cudaGetSymbolAddress((void**)&ktl, g_ktl);
    cudaGetSymbolAddress((void**)&vbh, g_vbh); cudaGetSymbolAddress((void**)&vbl, g_vbl);
    cudaGetSymbolAddress((void**)&rwh, g_rwh); cudaGetSymbolAddress((void**)&rwl, g_rwl);
    cudaGetSymbolAddress((void**)&qkvh, g_qkvh); cudaGetSymbolAddress((void**)&qkvl, g_qkvl);
    cudaGetSymbolAddress((void**)&woh, g_woh); cudaGetSymbolAddress((void**)&wol, g_wol);
    cudaGetSymbolAddress((void**)&w1h, g_w1h); cudaGetSymbolAddress((void**)&w1l, g_w1l);
    cudaGetSymbolAddress((void**)&w2h, g_w2h); cudaGetSymbolAddress((void**)&w2l, g_w2l);
    cudaGetSymbolAddress((void**)&pwh, g_pwh); cudaGetSymbolAddress((void**)&pwl, g_pwl);

    // ---- pre-split weights & x ----
    cvt_x_kernel<<<(200 * BATCH * XPAD + 255) / 256, 256>>>(x, xh, xl);
    cvt_kernel<<<(200 * RD * D + 255) / 256, 256>>>(roi_W, rwh, rwl, 200 * RD * D);
    cvt_kernel<<<(NL * 3 * D * D + 255) / 256, 256>>>(enc_Wqkv, qkvh, qkvl, NL * 3 * D * D);
    cvt_kernel<<<(NL * D * D + 255) / 256, 256>>>(enc_Wo, woh, wol, NL * D * D);
    cvt_kernel<<<(NL * D * FF + 255) / 256, 256>>>(enc_W1, w1h, w1l, NL * D * FF);
    cvt_kernel<<<(NL * FF * D + 255) / 256, 256>>>(enc_W2, w2h, w2l, NL * FF * D);
    cvt_kernel<<<(3 * D * D + 255) / 256, 256>>>(pool_Wqkv, pwh, pwl, 3 * D * D);

    // ---- tokenizer ----
    mma_gemm_kernel<<<dim3(2, 3, 200), 256>>>(xh, xl, rwh, rwl, roi_b,
        nullptr, nullptr, nullptr, raw, nullptr, nullptr,
        nullptr, nullptr, nullptr, nullptr, nullptr, nullptr, 2, RD, XPAD);
    tok_finish_kernel<<<MTOT / 8, 256>>>(raw, roi_lng, roi_lnb, pos_emb, h, hh, hl);

    // ---- encoder layers ----
    for (int l = 0; l < NL; ++l) {
        mma_gemm_kernel<<<dim3(MTOT / 128, 9, 1), 256>>>(hh, hl,
            qkvh + (size_t)l * 3 * D * D, qkvl + (size_t)l * 3 * D * D,
            enc_bqkv + (size_t)l * 3 * D,
            nullptr, nullptr, nullptr, nullptr, nullptr, nullptr,
            qbh, qbl, kth, ktl, vbh, vbl, 4, D, D);
        attn_mma_kernel<<<BATCH * NH, 256>>>(qbh, qbl, kth, ktl, vbh, vbl, ah, al);
        mma_gemm_kernel<<<dim3(MTOT / 128, 3, 1), 256>>>(ah, al,
            woh + (size_t)l * D * D, wol + (size_t)l * D * D, enc_bo + l * D,
            nullptr, nullptr, nullptr, raw, nullptr, nullptr,
            nullptr, nullptr, nullptr, nullptr, nullptr, nullptr, 3, D, D);
        addln_kernel<<<MTOT / 8, 256>>>(raw, h, enc_ln1g + l * D, enc_ln1b + l * D, h, hh, hl);
        mma_gemm_kernel<<<dim3(MTOT / 128, 9, 1), 256>>>(hh, hl,
            w1h + (size_t)l * D * FF, w1l + (size_t)l * D * FF, enc_b1 + l * FF,
            nullptr, nullptr, nullptr, nullptr, fh, fl,
            nullptr, nullptr, nullptr, nullptr, nullptr, nullptr, 1, D, D);
        mma_gemm_kernel<<<dim3(MTOT / 128, 3, 1), 256>>>(fh, fl,
            w2h + (size_t)l * FF * D, w2l + (size_t)l * FF * D, enc_b2 + l * D,
            nullptr, nullptr, nullptr, raw, nullptr, nullptr,
            nullptr, nullptr, nullptr, nullptr, nullptr, nullptr, 3, FF, FF);
        addln_kernel<<<MTOT / 8, 256>>>(raw, h, enc_ln2g + l * D, enc_ln2b + l * D, h, hh, hl);
    }

    // ---- pooling (fp32 QKV path) ----
    mma_gemm_kernel<<<dim3(MTOT / 128, 9, 1), 256>>>(hh, hl, pwh, pwl, pool_bqkv,
        q, k, v, nullptr, nullptr, nullptr,
        nullptr, nullptr, nullptr, nullptr, nullptr, nullptr, 0, D, D);
    pool_attn_kernel<<<BATCH * NH, 256>>>(q, k, v, pool);
    pool_proj_kernel<<<BATCH, 192>>>(pool, pool_Wo, pool_bo, pooled);

    // ---- classifier ----
    cls_kernel<<<BATCH, 192>>>(pooled, cls_lng, cls_lnb, cls_W1, cls_b1,
                               cls_W2, cls_b2, cls_W3, cls_b3, out);
}

// round 12
// speedup vs baseline: 1.1880x; 1.1880x over previous
#include <cuda_runtime.h>
#include <cuda_fp16.h>
#include <math.h>

#define BATCH 256
#define S 200
#define D 192
#define NH 6
#define DH 32
#define NL 3
#define FF 576
#define RD 199
#define MTOT (BATCH*S)
#define XPAD 224

typedef __half hf;

// ---------------- mma helpers -----------------------------------------------
__device__ __forceinline__ unsigned smem_u32(const void* p) {
    return (unsigned)__cvta_generic_to_shared(p);
}
__device__ __forceinline__ void ldsm_x4(unsigned addr, unsigned& r0, unsigned& r1,
                                        unsigned& r2, unsigned& r3) {
    asm volatile("ldmatrix.sync.aligned.m8n8.x4.shared.b16 {%0,%1,%2,%3}, [%4];"
                 : "=r"(r0), "=r"(r1), "=r"(r2), "=r"(r3) : "r"(addr));
}
__device__ __forceinline__ void ldsm_x4t(unsigned addr, unsigned& r0, unsigned& r1,
                                         unsigned& r2, unsigned& r3) {
    asm volatile("ldmatrix.sync.aligned.m8n8.x4.trans.shared.b16 {%0,%1,%2,%3}, [%4];"
                 : "=r"(r0), "=r"(r1), "=r"(r2), "=r"(r3) : "r"(addr));
}
__device__ __forceinline__ void mma16816(float c[4], const unsigned a[4], const unsigned b[2]) {
    asm volatile(
        "mma.sync.aligned.m16n8k16.row.col.f32.f16.f16.f32 "
        "{%0,%1,%2,%3}, {%4,%5,%6,%7}, {%8,%9}, {%0,%1,%2,%3};"
        : "+f"(c[0]), "+f"(c[1]), "+f"(c[2]), "+f"(c[3])
        : "r"(a[0]), "r"(a[1]), "r"(a[2]), "r"(a[3]), "r"(b[0]), "r"(b[1]));
}
__device__ __forceinline__ void split_hf(float x, hf& h, hf& l) {
    h = __float2half(x);
    l = __float2half(x - __half2float(h));
}
__device__ __forceinline__ unsigned pack_hf2(hf a, hf b) {
    __half2 t = __halves2half2(a, b);
    return *(unsigned*)&t;
}

// ---------------- scratch (device globals) ---------------------------------
__device__ float g_h[MTOT*D];
__device__ float g_raw[MTOT*D];
__device__ float g_q[MTOT*D];
__device__ float g_k[MTOT*D];
__device__ float g_v[MTOT*D];
__device__ float g_pool[BATCH*D];
__device__ float g_pooled[BATCH*D];

// fp16 hi/lo activation buffers (A-side: exact to 2^-22)
__device__ hf g_xh[200*BATCH*XPAD], g_xl[200*BATCH*XPAD];
__device__ hf g_hh[MTOT*D], g_hl[MTOT*D];
__device__ hf g_ah[MTOT*D], g_al[MTOT*D];
__device__ hf g_fh[MTOT*FF], g_fl[MTOT*FF];
// attention operands: Q split, K^T / V single fp16
__device__ hf g_qbh[MTOT*D], g_qbl[MTOT*D];   // [bh][s][dh] (pre-scaled)
__device__ hf g_kth[MTOT*D];                  // [bh][dh][s]
__device__ hf g_vbh[MTOT*D];                  // [bh][s][dh]
// single-fp16 weight buffers (B-side)
__device__ hf g_rwh[200*RD*D];
__device__ hf g_qkvh[NL*3*D*D];
__device__ hf g_woh[NL*D*D];
__device__ hf g_w1h[NL*D*FF];
__device__ hf g_w2h[NL*FF*D];
__device__ hf g_pwh[3*D*D];

__device__ __forceinline__ float gelu_exact(float x) {
    return 0.5f * x * (1.0f + erff(x * 0.70710678118654752f));
}

// ---------------- conversion kernels ----------------------------------------
__global__ void cvt1_kernel(const float* __restrict__ in, hf* __restrict__ o, int n)
{
    int i = blockIdx.x * 256 + threadIdx.x;
    if (i < n) o[i] = __float2half(in[i]);
}
__global__ void cvt_x_kernel(const float* __restrict__ x,
                             hf* __restrict__ hi, hf* __restrict__ lo)
{
    int i = blockIdx.x * 256 + threadIdx.x;
    if (i >= 200 * BATCH * XPAD) return;
    int k = i % XPAD; int tmp = i / XPAD;
    int b = tmp % BATCH; int roi = tmp / BATCH;
    float v = (k < RD) ? x[(size_t)b * (200 * RD) + roi * RD + k] : 0.f;
    hf h, l; split_hf(v, h, l);
    hi[i] = h; lo[i] = l;
}

// ============================================================================
// Tensor-core GEMM, fp16 A(hi/lo) x B(single), 2 MMAs/k16, reg prefetch.
// BM=128, BN=64, BK=32, 256 thr.
// mode 0: QKV fp32 scatter (pool); mode 1: FFN1 (+GELU) -> hf pair;
// mode 2: tokenizer raw fp32; mode 3: raw fp32 C; mode 4: QKV hf scatter + K^T.
// ============================================================================
__global__ __launch_bounds__(256) void mma_gemm_kernel(
    const hf* __restrict__ Ah, const hf* __restrict__ Al,
    const hf* __restrict__ Wh,
    const float* __restrict__ bias,
    float* __restrict__ oq, float* __restrict__ ok, float* __restrict__ ov,
    float* __restrict__ of, hf* __restrict__ obh, hf* __restrict__ obl,
    hf* __restrict__ xqh, hf* __restrict__ xql,
    hf* __restrict__ xkh, hf* __restrict__ xvh,
    int mode, int K, int lda)
{
    __shared__ hf AsH[128][40];
    __shared__ hf AsL[128][40];
    __shared__ hf BsH[32][72];

    int m0 = blockIdx.x * 128, n0 = blockIdx.y * 64, roi = blockIdx.z;
    int t = threadIdx.x;
    int warp = t >> 5, lane = t & 31;
    int wm = warp >> 1, wn = warp & 1;

    const hf* Bph; int ldb, nb;
    if (mode == 0 || mode == 4) {
        int wh = n0 / D;
        Bph = Wh + (size_t)wh * D * D;
        nb = n0 - wh * D; ldb = D;
    } else if (mode == 1) { Bph = Wh; nb = n0; ldb = FF; }
    else if (mode == 2) { Bph = Wh + (size_t)roi * RD * D; nb = n0; ldb = D; }
    else                { Bph = Wh; nb = n0; ldb = D; }

    if (mode == 2) {
        Ah += (size_t)roi * BATCH * XPAD;
        Al += (size_t)roi * BATCH * XPAD;
    }

    float acc[2][4][4] = {};

    // ---- preload tile 0 ----
#pragma unroll
    for (int p = t; p < 1024; p += 256) {
        int row = p >> 3, c4 = (p & 7) * 4;
        size_t off = (size_t)(m0 + row) * lda + c4;
        *(uint2*)&AsH[row][c4] = *(const uint2*)(Ah + off);
        *(uint2*)&AsL[row][c4] = *(const uint2*)(Al + off);
    }
#pragma unroll
    for (int p = t; p < 512; p += 256) {
        int k = p >> 4, n4 = (p & 15) * 4;
        uint2 zh = make_uint2(0u, 0u);
        if (k < K) zh = *(const uint2*)(Bph + (size_t)k * ldb + nb + n4);
        *(uint2*)&BsH[k][n4] = zh;
    }
    __syncthreads();

    for (int k0 = 0; k0 < K; k0 += 32) {
        bool has_next = (k0 + 32 < K);
        uint2 pa[4][2], pb[2];
        if (has_next) {
            int kn = k0 + 32;
#pragma unroll
            for (int i = 0; i < 4; ++i) {
                int p = t + i * 256;
                int row = p >> 3, c4 = (p & 7) * 4;
                size_t off = (size_t)(m0 + row) * lda + kn + c4;
                pa[i][0] = *(const uint2*)(Ah + off);
                pa[i][1] = *(const uint2*)(Al + off);
            }
#pragma unroll
            for (int i = 0; i < 2; ++i) {
                int p = t + i * 256;
                int k = p >> 4, n4 = (p & 15) * 4;
                uint2 zh = make_uint2(0u, 0u);
                if (kn + k < K) zh = *(const uint2*)(Bph + (size_t)(kn + k) * ldb + nb + n4);
                pb[i] = zh;
            }
        }

#pragma unroll
        for (int ks = 0; ks < 2; ++ks) {
            int kb = ks * 16;
            unsigned aH[2][4], aL[2][4];
            int aro = ((lane >> 3) & 1) * 8 + (lane & 7);
            int aco = kb + (lane >> 4) * 8;
#pragma unroll
            for (int mt = 0; mt < 2; ++mt) {
                int r = wm * 32 + mt * 16 + aro;
                ldsm_x4(smem_u32(&AsH[r][aco]), aH[mt][0], aH[mt][1], aH[mt][2], aH[mt][3]);
                ldsm_x4(smem_u32(&AsL[r][aco]), aL[mt][0], aL[mt][1], aL[mt][2], aL[mt][3]);
            }
            unsigned bH[4][2];
            int bro = kb + ((lane >> 3) & 1) * 8 + (lane & 7);
            int bco = wn * 32 + (lane >> 4) * 8;
#pragma unroll
            for (int np = 0; np < 2; ++np) {
                unsigned r0, r1, r2, r3;
                ldsm_x4t(smem_u32(&BsH[bro][bco + np * 16]), r0, r1, r2, r3);
                bH[np*2][0] = r0; bH[np*2][1] = r1; bH[np*2+1][0] = r2; bH[np*2+1][1] = r3;
            }
#pragma unroll
            for (int mt = 0; mt < 2; ++mt)
#pragma unroll
                for (int nt = 0; nt < 4; ++nt) {
                    mma16816(acc[mt][nt], aH[mt], bH[nt]);
                    mma16816(acc[mt][nt], aL[mt], bH[nt]);
                }
        }

        if (has_next) {
            __syncthreads();
#pragma unroll
            for (int i = 0; i < 4; ++i) {
                int p = t + i * 256;
                int row = p >> 3, c4 = (p & 7) * 4;
                *(uint2*)&AsH[row][c4] = pa[i][0];
                *(uint2*)&AsL[row][c4] = pa[i][1];
            }
#pragma unroll
            for (int i = 0; i < 2; ++i) {
                int p = t + i * 256;
                int k = p >> 4, n4 = (p & 15) * 4;
                *(uint2*)&BsH[k][n4] = pb[i];
            }
            __syncthreads();
        }
    }

    // ---- epilogue ----
    int g = lane >> 2, tq = (lane & 3) * 2;
#pragma unroll
    for (int mt = 0; mt < 2; ++mt) {
        int r0 = m0 + wm * 32 + mt * 16 + g;
#pragma unroll
        for (int nt = 0; nt < 4; ++nt) {
            float* c = acc[mt][nt];
            if (mode == 0) {
                int wh = n0 / D;
                int colq = nb + wn * 32 + nt * 8 + tq;
                int hd = colq >> 5, dh = colq & 31;
                float2 bb = *(const float2*)(bias + wh * D + colq);
                float* o = (wh == 0) ? oq : ((wh == 1) ? ok : ov);
                int m = r0;
                int b = m / S, s = m - b * S;
                *(float2*)(o + (((size_t)b * NH + hd) * S + s) * DH + dh)
                    = make_float2(c[0] + bb.x, c[1] + bb.y);
                m = r0 + 8; b = m / S; s = m - b * S;
                *(float2*)(o + (((size_t)b * NH + hd) * S + s) * DH + dh)
                    = make_float2(c[2] + bb.x, c[3] + bb.y);
            } else if (mode == 4) {
                int wh = n0 / D;
                int colq = nb + wn * 32 + nt * 8 + tq;
                int hd = colq >> 5, dh = colq & 31;
                float2 bb = *(const float2*)(bias + wh * D + colq);
#pragma unroll
                for (int rr = 0; rr < 2; ++rr) {
                    int m = r0 + rr * 8;
                    int b = m / S, s = m - b * S;
                    int bhq = b * NH + hd;
                    float f0 = c[rr * 2 + 0] + bb.x;
                    float f1 = c[rr * 2 + 1] + bb.y;
                    if (wh == 0) {
                        f0 *= 0.17677669529663687f; f1 *= 0.17677669529663687f;
                        hf h0, l0, h1, l1;
                        split_hf(f0, h0, l0); split_hf(f1, h1, l1);
                        size_t off = ((size_t)bhq * S + s) * DH + dh;
                        *(unsigned*)(xqh + off) = pack_hf2(h0, h1);
                        *(unsigned*)(xql + off) = pack_hf2(l0, l1);
                    } else if (wh == 1) {
                        size_t off = ((size_t)bhq * DH + dh) * S + s;
                        xkh[off]     = __float2half(f0);
                        xkh[off + S] = __float2half(f1);
                    } else {
                        size_t off = ((size_t)bhq * S + s) * DH + dh;
                        *(unsigned*)(xvh + off)
                            = pack_hf2(__float2half(f0), __float2half(f1));
                    }
                }
            } else if (mode == 1) {
                int col = n0 + wn * 32 + nt * 8 + tq;
                float2 bb = *(const float2*)(bias + col);
                float f0 = gelu_exact(c[0] + bb.x), f1 = gelu_exact(c[1] + bb.y);
                hf h0, l0, h1, l1;
                split_hf(f0, h0, l0); split_hf(f1, h1, l1);
                *(unsigned*)(obh + (size_t)r0 * FF + col) = pack_hf2(h0, h1);
                *(unsigned*)(obl + (size_t)r0 * FF + col) = pack_hf2(l0, l1);
                f0 = gelu_exact(c[2] + bb.x); f1 = gelu_exact(c[3] + bb.y);
                split_hf(f0, h0, l0); split_hf(f1, h1, l1);
                *(unsigned*)(obh + (size_t)(r0 + 8) * FF + col) = pack_hf2(h0, h1);
                *(unsigned*)(obl + (size_t)(r0 + 8) * FF + col) = pack_hf2(l0, l1);
            } else if (mode == 2) {
                int col = n0 + wn * 32 + nt * 8 + tq;
                float2 bb = *(const float2*)(bias + (size_t)roi * D + col);
                *(float2*)(of + ((size_t)r0 * S + roi) * D + col)
                    = make_float2(c[0] + bb.x, c[1] + bb.y);
                *(float2*)(of + ((size_t)(r0 + 8) * S + roi) * D + col)
                    = make_float2(c[2] + bb.x, c[3] + bb.y);
            } else {
                int col = n0 + wn * 32 + nt * 8 + tq;
                float2 bb = *(const float2*)(bias + col);
                *(float2*)(of + (size_t)r0 * D + col)
                    = make_float2(c[0] + bb.x, c[1] + bb.y);
                *(float2*)(of + (size_t)(r0 + 8) * D + col)
                    = make_float2(c[2] + bb.x, c[3] + bb.y);
            }
        }
    }
}

// ============================================================================
// Tensor-core attention: Q fp16 hi/lo, K/V single fp16; 2 MMAs/k16.
// CTA per (b,h), 8 warps, queries padded to 208, keys in 32-key tiles,
// register-prefetch K/V double buffer.
// ============================================================================
__global__ __launch_bounds__(256, 2) void attn_mma_kernel(
    const hf* __restrict__ qbh, const hf* __restrict__ qbl,
    const hf* __restrict__ kth, const hf* __restrict__ vbh,
    hf* __restrict__ oh, hf* __restrict__ ol)
{
    __shared__ hf Qh[208][40], Ql[208][40];
    __shared__ hf Kh[32][40];
    __shared__ hf Vh[32][40];

    int bh = blockIdx.x;
    int b = bh / NH, hd = bh - b * NH;
    int t = threadIdx.x, warp = t >> 5, lane = t & 31;
    int g = lane >> 2, tq = lane & 3;

    const hf* khb = kth + (size_t)bh * DH * S;
    const unsigned* vhp = (const unsigned*)(vbh + (size_t)bh * S * DH);
    const unsigned* qhp = (const unsigned*)(qbh + (size_t)bh * S * DH);
    const unsigned* qlp = (const unsigned*)(qbl + (size_t)bh * S * DH);

    for (int i = t; i < 208 * 16; i += 256) {
        int row = i >> 4, cp = i & 15;
        unsigned a = 0, c = 0;
        if (row < S) { a = qhp[row * 16 + cp]; c = qlp[row * 16 + cp]; }
        *(unsigned*)&Qh[row][cp * 2] = a;
        *(unsigned*)&Ql[row][cp * 2] = c;
    }
#pragma unroll
    for (int i = t; i < 512; i += 256) {
        int row = i >> 4, cp = i & 15;
        *(unsigned*)&Kh[row][cp * 2] = *(const unsigned*)(khb + row * S + cp * 2);
        *(unsigned*)&Vh[row][cp * 2] = vhp[row * 16 + cp];
    }
    __syncthreads();

    int nmt = (warp < 5) ? 2 : 1;
    int mt0 = warp * 16, mt1 = (8 + warp) * 16;
    int aro  = ((lane >> 3) & 1) * 8 + (lane & 7);
    int acoh = (lane >> 4) * 8;

    unsigned qH[2][2][4], qL[2][2][4];
    for (int mi = 0; mi < nmt; ++mi) {
        int mrow = mi ? mt1 : mt0;
#pragma unroll
        for (int ks = 0; ks < 2; ++ks) {
            ldsm_x4(smem_u32(&Qh[mrow + aro][ks * 16 + acoh]),
                    qH[mi][ks][0], qH[mi][ks][1], qH[mi][ks][2], qH[mi][ks][3]);
            ldsm_x4(smem_u32(&Ql[mrow + aro][ks * 16 + acoh]),
                    qL[mi][ks][0], qL[mi][ks][1], qL[mi][ks][2], qL[mi][ks][3]);
        }
    }

    float oacc[2][4][4] = {};
    float lsum[2][2] = {};

    for (int kt = 0; kt < 7; ++kt) {
        bool has_next = (kt < 6);
        unsigned pk[2], pv[2];
        if (has_next) {
            int kn0 = (kt + 1) * 32;
#pragma unroll
            for (int i = 0; i < 2; ++i) {
                int p = t + i * 256;
                int row = p >> 4, cp = p & 15;
                int key = kn0 + cp * 2;
                unsigned a = 0;
                if (key < S) a = *(const unsigned*)(khb + row * S + key);
                pk[i] = a;
                int keyv = kn0 + row;
                unsigned av = 0;
                if (keyv < S) av = vhp[keyv * 16 + cp];
                pv[i] = av;
            }
        }

        int kt0 = kt * 32;
        for (int mi = 0; mi < nmt; ++mi) {
#pragma unroll
            for (int kg = 0; kg < 2; ++kg) {
                float sc2[2][4] = {};
#pragma unroll
                for (int ks = 0; ks < 2; ++ks) {
                    unsigned kh2[2][2], r0, r1, r2, r3;
                    ldsm_x4t(smem_u32(&Kh[ks * 16 + aro][kg * 16 + acoh]), r0, r1, r2, r3);
                    kh2[0][0] = r0; kh2[0][1] = r1; kh2[1][0] = r2; kh2[1][1] = r3;
#pragma unroll
                    for (int j = 0; j < 2; ++j) {
                        mma16816(sc2[j], qH[mi][ks], kh2[j]);
                        mma16816(sc2[j], qL[mi][ks], kh2[j]);
                    }
                }
                float e[8];
#pragma unroll
                for (int j = 0; j < 2; ++j) {
                    int keyb = kt0 + (kg * 2 + j) * 8 + tq * 2;
                    float e0 = __expf(sc2[j][0]);
                    float e1 = __expf(sc2[j][1]);
                    float e2 = __expf(sc2[j][2]);
                    float e3 = __expf(sc2[j][3]);
                    if (keyb >= S)     { e0 = 0.f; e2 = 0.f; }
                    if (keyb + 1 >= S) { e1 = 0.f; e3 = 0.f; }
                    lsum[mi][0] += e0 + e1;
                    lsum[mi][1] += e2 + e3;
                    e[j * 4 + 0] = e0; e[j * 4 + 1] = e1;
                    e[j * 4 + 2] = e2; e[j * 4 + 3] = e3;
                }
                unsigned paH[4], paL[4];
                {
                    hf h0, l0, h1, l1;
                    split_hf(e[0], h0, l0); split_hf(e[1], h1, l1);
                    paH[0] = pack_hf2(h0, h1); paL[0] = pack_hf2(l0, l1);
                    split_hf(e[2], h0, l0); split_hf(e[3], h1, l1);
                    paH[1] = pack_hf2(h0, h1); paL[1] = pack_hf2(l0, l1);
                    split_hf(e[4], h0, l0); split_hf(e[5], h1, l1);
                    paH[2] = pack_hf2(h0, h1); paL[2] = pack_hf2(l0, l1);
                    split_hf(e[6], h0, l0); split_hf(e[7], h1, l1);
                    paH[3] = pack_hf2(h0, h1); paL[3] = pack_hf2(l0, l1);
                }
#pragma unroll
                for (int np = 0; np < 2; ++np) {
                    unsigned vh2[2][2], r0, r1, r2, r3;
                    ldsm_x4t(smem_u32(&Vh[kg * 16 + aro][np * 16 + acoh]), r0, r1, r2, r3);
                    vh2[0][0] = r0; vh2[0][1] = r1; vh2[1][0] = r2; vh2[1][1] = r3;
#pragma unroll
                    for (int j = 0; j < 2; ++j) {
                        int n8 = np * 2 + j;
                        mma16816(oacc[mi][n8], paH, vh2[j]);
                        mma16816(oacc[mi][n8], paL, vh2[j]);
                    }
                }
            }
        }

        if (has_next) {
            __syncthreads();
#pragma unroll
            for (int i = 0; i < 2; ++i) {
                int p = t + i * 256;
                int row = p >> 4, cp = p & 15;
                *(unsigned*)&Kh[row][cp * 2] = pk[i];
                *(unsigned*)&Vh[row][cp * 2] = pv[i];
            }
            __syncthreads();
        }
    }

    for (int mi = 0; mi < nmt; ++mi) {
        float l0 = lsum[mi][0], l1 = lsum[mi][1];
        l0 += __shfl_xor_sync(0xffffffffu, l0, 1);
        l0 += __shfl_xor_sync(0xffffffffu, l0, 2);
        l1 += __shfl_xor_sync(0xffffffffu, l1, 1);
        l1 += __shfl_xor_sync(0xffffffffu, l1, 2);
        float i0 = 1.f / l0, i1 = 1.f / l1;
        int mrow = mi ? mt1 : mt0;
        int s0 = mrow + g;
#pragma unroll
        for (int n8 = 0; n8 < 4; ++n8) {
            int col = hd * DH + n8 * 8 + tq * 2;
            if (s0 < S) {
                float u0 = oacc[mi][n8][0] * i0, u1 = oacc[mi][n8][1] * i0;
                hf h0, lo0, h1, lo1;
                split_hf(u0, h0, lo0); split_hf(u1, h1, lo1);
                size_t off = ((size_t)b * S + s0) * D + col;
                *(unsigned*)(oh + off) = pack_hf2(h0, h1);
                *(unsigned*)(ol + off) = pack_hf2(lo0, lo1);
            }
            if (s0 + 8 < S) {
                float u0 = oacc[mi][n8][2] * i1, u1 = oacc[mi][n8][3] * i1;
                hf h0, lo0, h1, lo1;
                split_hf(u0, h0, lo0); split_hf(u1, h1, lo1);
                size_t off = ((size_t)b * S + s0 + 8) * D + col;
                *(unsigned*)(oh + off) = pack_hf2(h0, h1);
                *(unsigned*)(ol + off) = pack_hf2(lo0, lo1);
            }
        }
    }
}

// ============================================================================
// add + LayerNorm: out = LN(raw + res) -> fp32 h + fp16 hi/lo
// ============================================================================
__global__ void addln_kernel(const float* __restrict__ raw,
                             const float* __restrict__ res,
                             const float* __restrict__ lng,
                             const float* __restrict__ lnb,
                             float* __restrict__ out,
                             hf* __restrict__ oh, hf* __restrict__ ol)
{
    int row = blockIdx.x * 8 + (threadIdx.x >> 5);
    int lane = threadIdx.x & 31;
    float vv[6];
    float sum = 0.f, sq = 0.f;
#pragma unroll
    for (int j = 0; j < 6; ++j) {
        int c = lane + 32 * j;
        vv[j] = raw[(size_t)row * D + c] + res[(size_t)row * D + c];
        sum += vv[j]; sq += vv[j] * vv[j];
    }
#pragma unroll
    for (int o = 16; o > 0; o >>= 1) {
        sum += __shfl_xor_sync(0xffffffffu, sum, o);
        sq  += __shfl_xor_sync(0xffffffffu, sq,  o);
    }
    float mean = sum * (1.f / D);
    float rstd = rsqrtf(sq * (1.f / D) - mean * mean + 1e-5f);
#pragma unroll
    for (int j = 0; j < 6; ++j) {
        int c = lane + 32 * j;
        float val = (vv[j] - mean) * rstd * lng[c] + lnb[c];
        out[(size_t)row * D + c] = val;
        hf h, l; split_hf(val, h, l);
        oh[(size_t)row * D + c] = h; ol[(size_t)row * D + c] = l;
    }
}

// ============================================================================
// token epilogue: per-roi LN + GELU + pos -> fp32 h + fp16 hi/lo
// ============================================================================
__global__ void tok_finish_kernel(const float* __restrict__ raw,
                                  const float* __restrict__ lng,
                                  const float* __restrict__ lnb,
                                  const float* __restrict__ pos,
                                  float* __restrict__ out,
                                  hf* __restrict__ oh, hf* __restrict__ ol)
{
    int row = blockIdx.x * 8 + (threadIdx.x >> 5);
    int roi = row % S;
    int lane = threadIdx.x & 31;
    float vv[6];
    float sum = 0.f, sq = 0.f;
#pragma unroll
    for (int j = 0; j < 6; ++j) {
        vv[j] = raw[(size_t)row * D + lane + 32 * j];
        sum += vv[j]; sq += vv[j] * vv[j];
    }
#pragma unroll
    for (int o = 16; o > 0; o >>= 1) {
        sum += __shfl_xor_sync(0xffffffffu, sum, o);
        sq  += __shfl_xor_sync(0xffffffffu, sq,  o);
    }
    float mean = sum * (1.f / D);
    float rstd = rsqrtf(sq * (1.f / D) - mean * mean + 1e-5f);
#pragma unroll
    for (int j = 0; j < 6; ++j) {
        int c = lane + 32 * j;
        float v = (vv[j] - mean) * rstd * lng[(size_t)roi * D + c] + lnb[(size_t)roi * D + c];
        float val = gelu_exact(v) + pos[(size_t)roi * D + c];
        out[(size_t)row * D + c] = val;
        hf h, l; split_hf(val, h, l);
        oh[(size_t)row * D + c] = h; ol[(size_t)row * D + c] = l;
    }
}

// ---------------- pooled attention (Q=1 via linearity) ---------------------
__global__ void pool_attn_kernel(const float* __restrict__ q,
                                 const float* __restrict__ k,
                                 const float* __restrict__ v,
                                 float* __restrict__ out)
{
    __shared__ float qm[DH];
    __shared__ float sc[S];
    __shared__ float red[2];
    int bh = blockIdx.x;
    int b = bh / NH, hd = bh % NH;
    size_t base = (size_t)bh * S * DH;
    int t = threadIdx.x;
    if (t < DH) {
        float s = 0.f;
        for (int j = 0; j < S; ++j) s += q[base + j * DH + t];
        qm[t] = s * (1.f / S) * 0.17677669529663687f;
    }
    __syncthreads();
    if (t < S) {
        float x = 0.f;
#pragma unroll
        for (int i = 0; i < DH; ++i) x += qm[i] * k[base + t * DH + i];
        sc[t] = x;
    }
    __syncthreads();
    if (t == 0) {
        float mx = -1e30f;
        for (int s = 0; s < S; ++s) mx = fmaxf(mx, sc[s]);
        red[0] = mx;
    }
    __syncthreads();
    if (t < S) sc[t] = __expf(sc[t] - red[0]);
    __syncthreads();
    if (t == 0) {
        float l = 0.f;
        for (int s = 0; s < S; ++s) l += sc[s];
        red[1] = 1.f / l;
    }
    __syncthreads();
    if (t < DH) {
        float o = 0.f;
        for (int s = 0; s < S; ++s) o += sc[s] * v[base + s * DH + t];
        out[(size_t)b * D + hd * DH + t] = o * red[1];
    }
}

// ---------------- pooled projection ----------------------------------------
__global__ void pool_proj_kernel(const float* __restrict__ in,
                                 const float* __restrict__ W,
                                 const float* __restrict__ bias,
                                 float* __restrict__ out)
{
    __shared__ float row[D];
    int b = blockIdx.x, d = threadIdx.x;
    row[d] = in[(size_t)b * D + d];
    __syncthreads();
    float s = bias[d];
    for (int k = 0; k < D; ++k) s += row[k] * W[(size_t)k * D + d];
    out[(size_t)b * D + d] = s;
}

// ---------------- classifier head ------------------------------------------
__global__ void cls_kernel(const float* __restrict__ in,
                           const float* __restrict__ g,  const float* __restrict__ bt,
                           const float* __restrict__ W1, const float* __restrict__ b1,
                           const float* __restrict__ W2, const float* __restrict__ b2,
                           const float* __restrict__ W3, const float* __restrict__ b3,
                           float* __restrict__ out)
{
    __shared__ float z[D];
    __shared__ float z1[96];
    __shared__ float z2[48];
    __shared__ float red[2];
    int b = blockIdx.x, t = threadIdx.x;
    float v = in[(size_t)b * D + t];
    z[t] = v;
    __syncthreads();
    if (t == 0) {
        float s = 0.f, sq = 0.f;
        for (int i = 0; i < D; ++i) { s += z[i]; sq += z[i] * z[i]; }
        float m = s / D;
        red[0] = m;
        red[1] = rsqrtf(sq / D - m * m + 1e-5f);
    }
    __syncthreads();
    z[t] = (v - red[0]) * red[1] * g[t] + bt[t];
    __syncthreads();
    if (t < 96) {
        float a = b1[t];
        for (int k = 0; k < D; ++k) a += z[k] * W1[k * 96 + t];
        z1[t] = gelu_exact(a);
    }
    __syncthreads();
    if (t < 48) {
        float a = b2[t];
        for (int k = 0; k < 96; ++k) a += z1[k] * W2[k * 48 + t];
        z2[t] = gelu_exact(a);
    }
    __syncthreads();
    if (t < 2) {
        float a = b3[t];
        for (int k = 0; k < 48; ++k) a += z2[k] * W3[k * 2 + t];
        out[(size_t)b * 2 + t] = a;
    }
}

// ---------------- launch ----------------------------------------------------
extern "C" void kernel_launch(void* const* d_in, const int* in_sizes, int n_in,
                              void* d_out, int out_size)
{
    const float* x        = (const float*)d_in[0];
    const float* roi_W    = (const float*)d_in[1];
    const float* roi_b    = (const float*)d_in[2];
    const float* roi_lng  = (const float*)d_in[3];
    const float* roi_lnb  = (const float*)d_in[4];
    const float* pos_emb  = (const float*)d_in[5];
    const float* enc_Wqkv = (const float*)d_in[6];
    const float* enc_bqkv = (const float*)d_in[7];
    const float* enc_Wo   = (const float*)d_in[8];
    const float* enc_bo   = (const float*)d_in[9];
    const float* enc_ln1g = (const float*)d_in[10];
    const float* enc_ln1b = (const float*)d_in[11];
    const float* enc_W1   = (const float*)d_in[12];
    const float* enc_b1   = (const float*)d_in[13];
    const float* enc_W2   = (const float*)d_in[14];
    const float* enc_b2   = (const float*)d_in[15];
    const float* enc_ln2g = (const float*)d_in[16];
    const float* enc_ln2b = (const float*)d_in[17];
    const float* pool_Wqkv= (const float*)d_in[18];
    const float* pool_bqkv= (const float*)d_in[19];
    const float* pool_Wo  = (const float*)d_in[20];
    const float* pool_bo  = (const float*)d_in[21];
    const float* cls_lng  = (const float*)d_in[22];
    const float* cls_lnb  = (const float*)d_in[23];
    const float* cls_W1   = (const float*)d_in[24];
    const float* cls_b1   = (const float*)d_in[25];
    const float* cls_W2   = (const float*)d_in[26];
    const float* cls_b2   = (const float*)d_in[27];
    const float* cls_W3   = (const float*)d_in[28];
    const float* cls_b3   = (const float*)d_in[29];
    float* out = (float*)d_out;

    float *h, *raw, *q, *k, *v, *pool, *pooled;
    hf *xh, *xl, *hh, *hl, *ah, *al, *fh, *fl;
    hf *qbh, *qbl, *kth, *vbh;
    hf *rwh, *qkvh, *woh, *w1h, *w2h, *pwh;
    cudaGetSymbolAddress((void**)&h,    g_h);
    cudaGetSymbolAddress((void**)&raw,  g_raw);
    cudaGetSymbolAddress((void**)&q,    g_q);
    cudaGetSymbolAddress((void**)&k,    g_k);
    cudaGetSymbolAddress((void**)&v,    g_v);
    cudaGetSymbolAddress((void**)&pool, g_pool);
    cudaGetSymbolAddress((void**)&pooled, g_pooled);
    cudaGetSymbolAddress((void**)&xh, g_xh);   cudaGetSymbolAddress((void**)&xl, g_xl);
    cudaGetSymbolAddress((void**)&hh, g_hh);   cudaGetSymbolAddress((void**)&hl, g_hl);
    cudaGetSymbolAddress((void**)&ah, g_ah);   cudaGetSymbolAddress((void**)&al, g_al);
    cudaGetSymbolAddress((void**)&fh, g_fh);   cudaGetSymbolAddress((void**)&fl, g_fl);
    cudaGetSymbolAddress((void**)&qbh, g_qbh); cudaGetSymbolAddress((void**)&qbl, g_qbl);
    cudaGetSymbolAddress((void**)&kth, g_kth);
    cudaGetSymbolAddress((void**)&vbh, g_vbh);
    cudaGetSymbolAddress((void**)&rwh, g_rwh);
    cudaGetSymbolAddress((void**)&qkvh, g_qkvh);
    cudaGetSymbolAddress((void**)&woh, g_woh);
    cudaGetSymbolAddress((void**)&w1h, g_w1h);
    cudaGetSymbolAddress((void**)&w2h, g_w2h);
    cudaGetSymbolAddress((void**)&pwh, g_pwh);

    // ---- pre-convert weights (single fp16) & x (split) ----
    cvt_x_kernel<<<(200 * BATCH * XPAD + 255) / 256, 256>>>(x, xh, xl);
    cvt1_kernel<<<(200 * RD * D + 255) / 256, 256>>>(roi_W, rwh, 200 * RD * D);
    cvt1_kernel<<<(NL * 3 * D * D + 255) / 256, 256>>>(enc_Wqkv, qkvh, NL * 3 * D * D);
    cvt1_kernel<<<(NL * D * D + 255) / 256, 256>>>(enc_Wo, woh, NL * D * D);
    cvt1_kernel<<<(NL * D * FF + 255) / 256, 256>>>(enc_W1, w1h, NL * D * FF);
    cvt1_kernel<<<(NL * FF * D + 255) / 256, 256>>>(enc_W2, w2h, NL * FF * D);
    cvt1_kernel<<<(3 * D * D + 255) / 256, 256>>>(pool_Wqkv, pwh, 3 * D * D);

    // ---- tokenizer ----
    mma_gemm_kernel<<<dim3(2, 3, 200), 256>>>(xh, xl, rwh, roi_b,
        nullptr, nullptr, nullptr, raw, nullptr, nullptr,
        nullptr, nullptr, nullptr, nullptr, 2, RD, XPAD);
    tok_finish_kernel<<<MTOT / 8, 256>>>(raw, roi_lng, roi_lnb, pos_emb, h, hh, hl);

    // ---- encoder layers ----
    for (int l = 0; l < NL; ++l) {
        mma_gemm_kernel<<<dim3(MTOT / 128, 9, 1), 256>>>(hh, hl,
            qkvh + (size_t)l * 3 * D * D, enc_bqkv + (size_t)l * 3 * D,
            nullptr, nullptr, nullptr, nullptr, nullptr, nullptr,
            qbh, qbl, kth, vbh, 4, D, D);
        attn_mma_kernel<<<BATCH * NH, 256>>>(qbh, qbl, kth, vbh, ah, al);
        mma_gemm_kernel<<<dim3(MTOT / 128, 3, 1), 256>>>(ah, al,
            woh + (size_t)l * D * D, enc_bo + l * D,
            nullptr, nullptr, nullptr, raw, nullptr, nullptr,
            nullptr, nullptr, nullptr, nullptr, 3, D, D);
        addln_kernel<<<MTOT / 8, 256>>>(raw, h, enc_ln1g + l * D, enc_ln1b + l * D, h, hh, hl);
        mma_gemm_kernel<<<dim3(MTOT / 128, 9, 1), 256>>>(hh, hl,
            w1h + (size_t)l * D * FF, enc_b1 + l * FF,
            nullptr, nullptr, nullptr, nullptr, fh, fl,
            nullptr, nullptr, nullptr, nullptr, 1, D, D);
        mma_gemm_kernel<<<dim3(MTOT / 128, 3, 1), 256>>>(fh, fl,
            w2h + (size_t)l * FF * D, enc_b2 + l * D,
            nullptr, nullptr, nullptr, raw, nullptr, nullptr,
            nullptr, nullptr, nullptr, nullptr, 3, FF, FF);
        addln_kernel<<<MTOT / 8, 256>>>(raw, h, enc_ln2g + l * D, enc_ln2b + l * D, h, hh, hl);
    }

    // ---- pooling (fp32 QKV path) ----
    mma_gemm_kernel<<<dim3(MTOT / 128, 9, 1), 256>>>(hh, hl, pwh, pool_bqkv,
        q, k, v, nullptr, nullptr, nullptr,
        nullptr, nullptr, nullptr, nullptr, 0, D, D);
    pool_attn_kernel<<<BATCH * NH, 256>>>(q, k, v, pool);
    pool_proj_kernel<<<BATCH, 192>>>(pool, pool_Wo, pool_bo, pooled);

    // ---- classifier ----
    cls_kernel<<<BATCH, 192>>>(pooled, cls_lng, cls_lnb, cls_W1, cls_b1,
                               cls_W2, cls_b2, cls_W3, cls_b3, out);
}

// round 13
// speedup vs baseline: 1.5718x; 1.3231x over previous
#include <cuda_runtime.h>
#include <cuda_fp16.h>
#include <math.h>

#define BATCH 256
#define S 200
#define D 192
#define NH 6
#define DH 32
#define NL 3
#define FF 576
#define RD 199
#define MTOT (BATCH*S)
#define XPAD 224

typedef __half hf;

// ---------------- mma helpers -----------------------------------------------
__device__ __forceinline__ unsigned smem_u32(const void* p) {
    return (unsigned)__cvta_generic_to_shared(p);
}
__device__ __forceinline__ void ldsm_x4(unsigned addr, unsigned& r0, unsigned& r1,
                                        unsigned& r2, unsigned& r3) {
    asm volatile("ldmatrix.sync.aligned.m8n8.x4.shared.b16 {%0,%1,%2,%3}, [%4];"
                 : "=r"(r0), "=r"(r1), "=r"(r2), "=r"(r3) : "r"(addr));
}
__device__ __forceinline__ void ldsm_x4t(unsigned addr, unsigned& r0, unsigned& r1,
                                         unsigned& r2, unsigned& r3) {
    asm volatile("ldmatrix.sync.aligned.m8n8.x4.trans.shared.b16 {%0,%1,%2,%3}, [%4];"
                 : "=r"(r0), "=r"(r1), "=r"(r2), "=r"(r3) : "r"(addr));
}
__device__ __forceinline__ void mma16816(float c[4], const unsigned a[4], const unsigned b[2]) {
    asm volatile(
        "mma.sync.aligned.m16n8k16.row.col.f32.f16.f16.f32 "
        "{%0,%1,%2,%3}, {%4,%5,%6,%7}, {%8,%9}, {%0,%1,%2,%3};"
        : "+f"(c[0]), "+f"(c[1]), "+f"(c[2]), "+f"(c[3])
        : "r"(a[0]), "r"(a[1]), "r"(a[2]), "r"(a[3]), "r"(b[0]), "r"(b[1]));
}
__device__ __forceinline__ void split_hf(float x, hf& h, hf& l) {
    h = __float2half(x);
    l = __float2half(x - __half2float(h));
}
__device__ __forceinline__ unsigned pack_hf2(hf a, hf b) {
    __half2 t = __halves2half2(a, b);
    return *(unsigned*)&t;
}

// ---------------- scratch (device globals) ---------------------------------
__device__ float g_h[MTOT*D];
__device__ float g_raw[MTOT*D];
__device__ float g_q[MTOT*D];
__device__ float g_k[MTOT*D];
__device__ float g_v[MTOT*D];
__device__ float g_pool[BATCH*D];
__device__ float g_pooled[BATCH*D];

// fp16 activation buffers (single precision A-side for GEMMs)
__device__ hf g_xh[200*BATCH*XPAD];
__device__ hf g_hh[MTOT*D];
__device__ hf g_ah[MTOT*D];
__device__ hf g_fh[MTOT*FF];
// attention operands: Q split (kept), K^T / V single fp16
__device__ hf g_qbh[MTOT*D], g_qbl[MTOT*D];   // [bh][s][dh] (pre-scaled)
__device__ hf g_kth[MTOT*D];                  // [bh][dh][s]
__device__ hf g_vbh[MTOT*D];                  // [bh][s][dh]
// single-fp16 weight buffers
__device__ hf g_rwh[200*RD*D];
__device__ hf g_qkvh[NL*3*D*D];
__device__ hf g_woh[NL*D*D];
__device__ hf g_w1h[NL*D*FF];
__device__ hf g_w2h[NL*FF*D];
__device__ hf g_pwh[3*D*D];

__device__ __forceinline__ float gelu_exact(float x) {
    return 0.5f * x * (1.0f + erff(x * 0.70710678118654752f));
}

// ---------------- conversion kernels ----------------------------------------
__global__ void cvt1_kernel(const float* __restrict__ in, hf* __restrict__ o, int n)
{
    int i = blockIdx.x * 256 + threadIdx.x;
    if (i < n) o[i] = __float2half(in[i]);
}
__global__ void cvt_x_kernel(const float* __restrict__ x, hf* __restrict__ hi)
{
    int i = blockIdx.x * 256 + threadIdx.x;
    if (i >= 200 * BATCH * XPAD) return;
    int k = i % XPAD; int tmp = i / XPAD;
    int b = tmp % BATCH; int roi = tmp / BATCH;
    float v = (k < RD) ? x[(size_t)b * (200 * RD) + roi * RD + k] : 0.f;
    hi[i] = __float2half(v);
}

// ============================================================================
// Tensor-core GEMM, fp16 x fp16 (1 MMA/k16), register-prefetch double buffer.
// BM=128, BN=64, BK=32, 256 thr.
// mode 0: QKV fp32 scatter (pool); mode 1: FFN1 (+GELU) -> hf;
// mode 2: tokenizer raw fp32; mode 3: raw fp32 C; mode 4: QKV hf scatter + K^T.
// ============================================================================
__global__ __launch_bounds__(256) void mma_gemm_kernel(
    const hf* __restrict__ Ah,
    const hf* __restrict__ Wh,
    const float* __restrict__ bias,
    float* __restrict__ oq, float* __restrict__ ok, float* __restrict__ ov,
    float* __restrict__ of, hf* __restrict__ obh,
    hf* __restrict__ xqh, hf* __restrict__ xql,
    hf* __restrict__ xkh, hf* __restrict__ xvh,
    int mode, int K, int lda)
{
    __shared__ hf AsH[128][40];
    __shared__ hf BsH[32][72];

    int m0 = blockIdx.x * 128, n0 = blockIdx.y * 64, roi = blockIdx.z;
    int t = threadIdx.x;
    int warp = t >> 5, lane = t & 31;
    int wm = warp >> 1, wn = warp & 1;

    const hf* Bph; int ldb, nb;
    if (mode == 0 || mode == 4) {
        int wh = n0 / D;
        Bph = Wh + (size_t)wh * D * D;
        nb = n0 - wh * D; ldb = D;
    } else if (mode == 1) { Bph = Wh; nb = n0; ldb = FF; }
    else if (mode == 2) { Bph = Wh + (size_t)roi * RD * D; nb = n0; ldb = D; }
    else                { Bph = Wh; nb = n0; ldb = D; }

    if (mode == 2) Ah += (size_t)roi * BATCH * XPAD;

    float acc[2][4][4] = {};

    // ---- preload tile 0 ----
#pragma unroll
    for (int p = t; p < 1024; p += 256) {
        int row = p >> 3, c4 = (p & 7) * 4;
        *(uint2*)&AsH[row][c4] = *(const uint2*)(Ah + (size_t)(m0 + row) * lda + c4);
    }
#pragma unroll
    for (int p = t; p < 512; p += 256) {
        int k = p >> 4, n4 = (p & 15) * 4;
        uint2 zh = make_uint2(0u, 0u);
        if (k < K) zh = *(const uint2*)(Bph + (size_t)k * ldb + nb + n4);
        *(uint2*)&BsH[k][n4] = zh;
    }
    __syncthreads();

    for (int k0 = 0; k0 < K; k0 += 32) {
        bool has_next = (k0 + 32 < K);
        uint2 pa[4], pb[2];
        if (has_next) {
            int kn = k0 + 32;
#pragma unroll
            for (int i = 0; i < 4; ++i) {
                int p = t + i * 256;
                int row = p >> 3, c4 = (p & 7) * 4;
                pa[i] = *(const uint2*)(Ah + (size_t)(m0 + row) * lda + kn + c4);
            }
#pragma unroll
            for (int i = 0; i < 2; ++i) {
                int p = t + i * 256;
                int k = p >> 4, n4 = (p & 15) * 4;
                uint2 zh = make_uint2(0u, 0u);
                if (kn + k < K) zh = *(const uint2*)(Bph + (size_t)(kn + k) * ldb + nb + n4);
                pb[i] = zh;
            }
        }

#pragma unroll
        for (int ks = 0; ks < 2; ++ks) {
            int kb = ks * 16;
            unsigned aH[2][4];
            int aro = ((lane >> 3) & 1) * 8 + (lane & 7);
            int aco = kb + (lane >> 4) * 8;
#pragma unroll
            for (int mt = 0; mt < 2; ++mt) {
                int r = wm * 32 + mt * 16 + aro;
                ldsm_x4(smem_u32(&AsH[r][aco]), aH[mt][0], aH[mt][1], aH[mt][2], aH[mt][3]);
            }
            unsigned bH[4][2];
            int bro = kb + ((lane >> 3) & 1) * 8 + (lane & 7);
            int bco = wn * 32 + (lane >> 4) * 8;
#pragma unroll
            for (int np = 0; np < 2; ++np) {
                unsigned r0, r1, r2, r3;
                ldsm_x4t(smem_u32(&BsH[bro][bco + np * 16]), r0, r1, r2, r3);
                bH[np*2][0] = r0; bH[np*2][1] = r1; bH[np*2+1][0] = r2; bH[np*2+1][1] = r3;
            }
#pragma unroll
            for (int mt = 0; mt < 2; ++mt)
#pragma unroll
                for (int nt = 0; nt < 4; ++nt)
                    mma16816(acc[mt][nt], aH[mt], bH[nt]);
        }

        if (has_next) {
            __syncthreads();
#pragma unroll
            for (int i = 0; i < 4; ++i) {
                int p = t + i * 256;
                int row = p >> 3, c4 = (p & 7) * 4;
                *(uint2*)&AsH[row][c4] = pa[i];
            }
#pragma unroll
            for (int i = 0; i < 2; ++i) {
                int p = t + i * 256;
                int k = p >> 4, n4 = (p & 15) * 4;
                *(uint2*)&BsH[k][n4] = pb[i];
            }
            __syncthreads();
        }
    }

    // ---- epilogue ----
    int g = lane >> 2, tq = (lane & 3) * 2;
#pragma unroll
    for (int mt = 0; mt < 2; ++mt) {
        int r0 = m0 + wm * 32 + mt * 16 + g;
#pragma unroll
        for (int nt = 0; nt < 4; ++nt) {
            float* c = acc[mt][nt];
            if (mode == 0) {
                int wh = n0 / D;
                int colq = nb + wn * 32 + nt * 8 + tq;
                int hd = colq >> 5, dh = colq & 31;
                float2 bb = *(const float2*)(bias + wh * D + colq);
                float* o = (wh == 0) ? oq : ((wh == 1) ? ok : ov);
                int m = r0;
                int b = m / S, s = m - b * S;
                *(float2*)(o + (((size_t)b * NH + hd) * S + s) * DH + dh)
                    = make_float2(c[0] + bb.x, c[1] + bb.y);
                m = r0 + 8; b = m / S; s = m - b * S;
                *(float2*)(o + (((size_t)b * NH + hd) * S + s) * DH + dh)
                    = make_float2(c[2] + bb.x, c[3] + bb.y);
            } else if (mode == 4) {
                int wh = n0 / D;
                int colq = nb + wn * 32 + nt * 8 + tq;
                int hd = colq >> 5, dh = colq & 31;
                float2 bb = *(const float2*)(bias + wh * D + colq);
#pragma unroll
                for (int rr = 0; rr < 2; ++rr) {
                    int m = r0 + rr * 8;
                    int b = m / S, s = m - b * S;
                    int bhq = b * NH + hd;
                    float f0 = c[rr * 2 + 0] + bb.x;
                    float f1 = c[rr * 2 + 1] + bb.y;
                    if (wh == 0) {
                        f0 *= 0.17677669529663687f; f1 *= 0.17677669529663687f;
                        hf h0, l0, h1, l1;
                        split_hf(f0, h0, l0); split_hf(f1, h1, l1);
                        size_t off = ((size_t)bhq * S + s) * DH + dh;
                        *(unsigned*)(xqh + off) = pack_hf2(h0, h1);
                        *(unsigned*)(xql + off) = pack_hf2(l0, l1);
                    } else if (wh == 1) {
                        size_t off = ((size_t)bhq * DH + dh) * S + s;
                        xkh[off]     = __float2half(f0);
                        xkh[off + S] = __float2half(f1);
                    } else {
                        size_t off = ((size_t)bhq * S + s) * DH + dh;
                        *(unsigned*)(xvh + off)
                            = pack_hf2(__float2half(f0), __float2half(f1));
                    }
                }
            } else if (mode == 1) {
                int col = n0 + wn * 32 + nt * 8 + tq;
                float2 bb = *(const float2*)(bias + col);
                float f0 = gelu_exact(c[0] + bb.x), f1 = gelu_exact(c[1] + bb.y);
                *(unsigned*)(obh + (size_t)r0 * FF + col)
                    = pack_hf2(__float2half(f0), __float2half(f1));
                f0 = gelu_exact(c[2] + bb.x); f1 = gelu_exact(c[3] + bb.y);
                *(unsigned*)(obh + (size_t)(r0 + 8) * FF + col)
                    = pack_hf2(__float2half(f0), __float2half(f1));
            } else if (mode == 2) {
                int col = n0 + wn * 32 + nt * 8 + tq;
                float2 bb = *(const float2*)(bias + (size_t)roi * D + col);
                *(float2*)(of + ((size_t)r0 * S + roi) * D + col)
                    = make_float2(c[0] + bb.x, c[1] + bb.y);
                *(float2*)(of + ((size_t)(r0 + 8) * S + roi) * D + col)
                    = make_float2(c[2] + bb.x, c[3] + bb.y);
            } else {
                int col = n0 + wn * 32 + nt * 8 + tq;
                float2 bb = *(const float2*)(bias + col);
                *(float2*)(of + (size_t)r0 * D + col)
                    = make_float2(c[0] + bb.x, c[1] + bb.y);
                *(float2*)(of + (size_t)(r0 + 8) * D + col)
                    = make_float2(c[2] + bb.x, c[3] + bb.y);
            }
        }
    }
}

// ============================================================================
// Tensor-core attention: Q fp16 hi/lo, K/V single fp16, P hi/lo (unchanged).
// ============================================================================
__global__ __launch_bounds__(256, 2) void attn_mma_kernel(
    const hf* __restrict__ qbh, const hf* __restrict__ qbl,
    const hf* __restrict__ kth, const hf* __restrict__ vbh,
    hf* __restrict__ oh)
{
    __shared__ hf Qh[208][40], Ql[208][40];
    __shared__ hf Kh[32][40];
    __shared__ hf Vh[32][40];

    int bh = blockIdx.x;
    int b = bh / NH, hd = bh - b * NH;
    int t = threadIdx.x, warp = t >> 5, lane = t & 31;
    int g = lane >> 2, tq = lane & 3;

    const hf* khb = kth + (size_t)bh * DH * S;
    const unsigned* vhp = (const unsigned*)(vbh + (size_t)bh * S * DH);
    const unsigned* qhp = (const unsigned*)(qbh + (size_t)bh * S * DH);
    const unsigned* qlp = (const unsigned*)(qbl + (size_t)bh * S * DH);

    for (int i = t; i < 208 * 16; i += 256) {
        int row = i >> 4, cp = i & 15;
        unsigned a = 0, c = 0;
        if (row < S) { a = qhp[row * 16 + cp]; c = qlp[row * 16 + cp]; }
        *(unsigned*)&Qh[row][cp * 2] = a;
        *(unsigned*)&Ql[row][cp * 2] = c;
    }
#pragma unroll
    for (int i = t; i < 512; i += 256) {
        int row = i >> 4, cp = i & 15;
        *(unsigned*)&Kh[row][cp * 2] = *(const unsigned*)(khb + row * S + cp * 2);
        *(unsigned*)&Vh[row][cp * 2] = vhp[row * 16 + cp];
    }
    __syncthreads();

    int nmt = (warp < 5) ? 2 : 1;
    int mt0 = warp * 16, mt1 = (8 + warp) * 16;
    int aro  = ((lane >> 3) & 1) * 8 + (lane & 7);
    int acoh = (lane >> 4) * 8;

    unsigned qH[2][2][4], qL[2][2][4];
    for (int mi = 0; mi < nmt; ++mi) {
        int mrow = mi ? mt1 : mt0;
#pragma unroll
        for (int ks = 0; ks < 2; ++ks) {
            ldsm_x4(smem_u32(&Qh[mrow + aro][ks * 16 + acoh]),
                    qH[mi][ks][0], qH[mi][ks][1], qH[mi][ks][2], qH[mi][ks][3]);
            ldsm_x4(smem_u32(&Ql[mrow + aro][ks * 16 + acoh]),
                    qL[mi][ks][0], qL[mi][ks][1], qL[mi][ks][2], qL[mi][ks][3]);
        }
    }

    float oacc[2][4][4] = {};
    float lsum[2][2] = {};

    for (int kt = 0; kt < 7; ++kt) {
        bool has_next = (kt < 6);
        unsigned pk[2], pv[2];
        if (has_next) {
            int kn0 = (kt + 1) * 32;
#pragma unroll
            for (int i = 0; i < 2; ++i) {
                int p = t + i * 256;
                int row = p >> 4, cp = p & 15;
                int key = kn0 + cp * 2;
                unsigned a = 0;
                if (key < S) a = *(const unsigned*)(khb + row * S + key);
                pk[i] = a;
                int keyv = kn0 + row;
                unsigned av = 0;
                if (keyv < S) av = vhp[keyv * 16 + cp];
                pv[i] = av;
            }
        }

        int kt0 = kt * 32;
        for (int mi = 0; mi < nmt; ++mi) {
#pragma unroll
            for (int kg = 0; kg < 2; ++kg) {
                float sc2[2][4] = {};
#pragma unroll
                for (int ks = 0; ks < 2; ++ks) {
                    unsigned kh2[2][2], r0, r1, r2, r3;
                    ldsm_x4t(smem_u32(&Kh[ks * 16 + aro][kg * 16 + acoh]), r0, r1, r2, r3);
                    kh2[0][0] = r0; kh2[0][1] = r1; kh2[1][0] = r2; kh2[1][1] = r3;
#pragma unroll
                    for (int j = 0; j < 2; ++j) {
                        mma16816(sc2[j], qH[mi][ks], kh2[j]);
                        mma16816(sc2[j], qL[mi][ks], kh2[j]);
                    }
                }
                float e[8];
#pragma unroll
                for (int j = 0; j < 2; ++j) {
                    int keyb = kt0 + (kg * 2 + j) * 8 + tq * 2;
                    float e0 = __expf(sc2[j][0]);
                    float e1 = __expf(sc2[j][1]);
                    float e2 = __expf(sc2[j][2]);
                    float e3 = __expf(sc2[j][3]);
                    if (keyb >= S)     { e0 = 0.f; e2 = 0.f; }
                    if (keyb + 1 >= S) { e1 = 0.f; e3 = 0.f; }
                    lsum[mi][0] += e0 + e1;
                    lsum[mi][1] += e2 + e3;
                    e[j * 4 + 0] = e0; e[j * 4 + 1] = e1;
                    e[j * 4 + 2] = e2; e[j * 4 + 3] = e3;
                }
                unsigned paH[4], paL[4];
                {
                    hf h0, l0, h1, l1;
                    split_hf(e[0], h0, l0); split_hf(e[1], h1, l1);
                    paH[0] = pack_hf2(h0, h1); paL[0] = pack_hf2(l0, l1);
                    split_hf(e[2], h0, l0); split_hf(e[3], h1, l1);
                    paH[1] = pack_hf2(h0, h1); paL[1] = pack_hf2(l0, l1);
                    split_hf(e[4], h0, l0); split_hf(e[5], h1, l1);
                    paH[2] = pack_hf2(h0, h1); paL[2] = pack_hf2(l0, l1);
                    split_hf(e[6], h0, l0); split_hf(e[7], h1, l1);
                    paH[3] = pack_hf2(h0, h1); paL[3] = pack_hf2(l0, l1);
                }
#pragma unroll
                for (int np = 0; np < 2; ++np) {
                    unsigned vh2[2][2], r0, r1, r2, r3;
                    ldsm_x4t(smem_u32(&Vh[kg * 16 + aro][np * 16 + acoh]), r0, r1, r2, r3);
                    vh2[0][0] = r0; vh2[0][1] = r1; vh2[1][0] = r2; vh2[1][1] = r3;
#pragma unroll
                    for (int j = 0; j < 2; ++j) {
                        int n8 = np * 2 + j;
                        mma16816(oacc[mi][n8], paH, vh2[j]);
                        mma16816(oacc[mi][n8], paL, vh2[j]);
                    }
                }
            }
        }

        if (has_next) {
            __syncthreads();
#pragma unroll
            for (int i = 0; i < 2; ++i) {
                int p = t + i * 256;
                int row = p >> 4, cp = p & 15;
                *(unsigned*)&Kh[row][cp * 2] = pk[i];
                *(unsigned*)&Vh[row][cp * 2] = pv[i];
            }
            __syncthreads();
        }
    }

    for (int mi = 0; mi < nmt; ++mi) {
        float l0 = lsum[mi][0], l1 = lsum[mi][1];
        l0 += __shfl_xor_sync(0xffffffffu, l0, 1);
        l0 += __shfl_xor_sync(0xffffffffu, l0, 2);
        l1 += __shfl_xor_sync(0xffffffffu, l1, 1);
        l1 += __shfl_xor_sync(0xffffffffu, l1, 2);
        float i0 = 1.f / l0, i1 = 1.f / l1;
        int mrow = mi ? mt1 : mt0;
        int s0 = mrow + g;
#pragma unroll
        for (int n8 = 0; n8 < 4; ++n8) {
            int col = hd * DH + n8 * 8 + tq * 2;
            if (s0 < S) {
                float u0 = oacc[mi][n8][0] * i0, u1 = oacc[mi][n8][1] * i0;
                size_t off = ((size_t)b * S + s0) * D + col;
                *(unsigned*)(oh + off) = pack_hf2(__float2half(u0), __float2half(u1));
            }
            if (s0 + 8 < S) {
                float u0 = oacc[mi][n8][2] * i1, u1 = oacc[mi][n8][3] * i1;
                size_t off = ((size_t)b * S + s0 + 8) * D + col;
                *(unsigned*)(oh + off) = pack_hf2(__float2half(u0), __float2half(u1));
            }
        }
    }
}

// ============================================================================
// add + LayerNorm: out = LN(raw + res) -> fp32 h + fp16
// ============================================================================
__global__ void addln_kernel(const float* __restrict__ raw,
                             const float* __restrict__ res,
                             const float* __restrict__ lng,
                             const float* __restrict__ lnb,
                             float* __restrict__ out,
                             hf* __restrict__ oh)
{
    int row = blockIdx.x * 8 + (threadIdx.x >> 5);
    int lane = threadIdx.x & 31;
    float vv[6];
    float sum = 0.f, sq = 0.f;
#pragma unroll
    for (int j = 0; j < 6; ++j) {
        int c = lane + 32 * j;
        vv[j] = raw[(size_t)row * D + c] + res[(size_t)row * D + c];
        sum += vv[j]; sq += vv[j] * vv[j];
    }
#pragma unroll
    for (int o = 16; o > 0; o >>= 1) {
        sum += __shfl_xor_sync(0xffffffffu, sum, o);
        sq  += __shfl_xor_sync(0xffffffffu, sq,  o);
    }
    float mean = sum * (1.f / D);
    float rstd = rsqrtf(sq * (1.f / D) - mean * mean + 1e-5f);
#pragma unroll
    for (int j = 0; j < 6; ++j) {
        int c = lane + 32 * j;
        float val = (vv[j] - mean) * rstd * lng[c] + lnb[c];
        out[(size_t)row * D + c] = val;
        oh[(size_t)row * D + c] = __float2half(val);
    }
}

// ============================================================================
// token epilogue: per-roi LN + GELU + pos -> fp32 h + fp16
// ============================================================================
__global__ void tok_finish_kernel(const float* __restrict__ raw,
                                  const float* __restrict__ lng,
                                  const float* __restrict__ lnb,
                                  const float* __restrict__ pos,
                                  float* __restrict__ out,
                                  hf* __restrict__ oh)
{
    int row = blockIdx.x * 8 + (threadIdx.x >> 5);
    int roi = row % S;
    int lane = threadIdx.x & 31;
    float vv[6];
    float sum = 0.f, sq = 0.f;
#pragma unroll
    for (int j = 0; j < 6; ++j) {
        vv[j] = raw[(size_t)row * D + lane + 32 * j];
        sum += vv[j]; sq += vv[j] * vv[j];
    }
#pragma unroll
    for (int o = 16; o > 0; o >>= 1) {
        sum += __shfl_xor_sync(0xffffffffu, sum, o);
        sq  += __shfl_xor_sync(0xffffffffu, sq,  o);
    }
    float mean = sum * (1.f / D);
    float rstd = rsqrtf(sq * (1.f / D) - mean * mean + 1e-5f);
#pragma unroll
    for (int j = 0; j < 6; ++j) {
        int c = lane + 32 * j;
        float v = (vv[j] - mean) * rstd * lng[(size_t)roi * D + c] + lnb[(size_t)roi * D + c];
        float val = gelu_exact(v) + pos[(size_t)roi * D + c];
        out[(size_t)row * D + c] = val;
        oh[(size_t)row * D + c] = __float2half(val);
    }
}

// ---------------- pooled attention (Q=1 via linearity) ---------------------
__global__ void pool_attn_kernel(const float* __restrict__ q,
                                 const float* __restrict__ k,
                                 const float* __restrict__ v,
                                 float* __restrict__ out)
{
    __shared__ float qm[DH];
    __shared__ float sc[S];
    __shared__ float red[2];
    int bh = blockIdx.x;
    int b = bh / NH, hd = bh % NH;
    size_t base = (size_t)bh * S * DH;
    int t = threadIdx.x;
    if (t < DH) {
        float s = 0.f;
        for (int j = 0; j < S; ++j) s += q[base + j * DH + t];
        qm[t] = s * (1.f / S) * 0.17677669529663687f;
    }
    __syncthreads();
    if (t < S) {
        float x = 0.f;
#pragma unroll
        for (int i = 0; i < DH; ++i) x += qm[i] * k[base + t * DH + i];
        sc[t] = x;
    }
    __syncthreads();
    if (t == 0) {
        float mx = -1e30f;
        for (int s = 0; s < S; ++s) mx = fmaxf(mx, sc[s]);
        red[0] = mx;
    }
    __syncthreads();
    if (t < S) sc[t] = __expf(sc[t] - red[0]);
    __syncthreads();
    if (t == 0) {
        float l = 0.f;
        for (int s = 0; s < S; ++s) l += sc[s];
        red[1] = 1.f / l;
    }
    __syncthreads();
    if (t < DH) {
        float o = 0.f;
        for (int s = 0; s < S; ++s) o += sc[s] * v[base + s * DH + t];
        out[(size_t)b * D + hd * DH + t] = o * red[1];
    }
}

// ---------------- pooled projection ----------------------------------------
__global__ void pool_proj_kernel(const float* __restrict__ in,
                                 const float* __restrict__ W,
                                 const float* __restrict__ bias,
                                 float* __restrict__ out)
{
    __shared__ float row[D];
    int b = blockIdx.x, d = threadIdx.x;
    row[d] = in[(size_t)b * D + d];
    __syncthreads();
    float s = bias[d];
    for (int k = 0; k < D; ++k) s += row[k] * W[(size_t)k * D + d];
    out[(size_t)b * D + d] = s;
}

// ---------------- classifier head ------------------------------------------
__global__ void cls_kernel(const float* __restrict__ in,
                           const float* __restrict__ g,  const float* __restrict__ bt,
                           const float* __restrict__ W1, const float* __restrict__ b1,
                           const float* __restrict__ W2, const float* __restrict__ b2,
                           const float* __restrict__ W3, const float* __restrict__ b3,
                           float* __restrict__ out)
{
    __shared__ float z[D];
    __shared__ float z1[96];
    __shared__ float z2[48];
    __shared__ float red[2];
    int b = blockIdx.x, t = threadIdx.x;
    float v = in[(size_t)b * D + t];
    z[t] = v;
    __syncthreads();
    if (t == 0) {
        float s = 0.f, sq = 0.f;
        for (int i = 0; i < D; ++i) { s += z[i]; sq += z[i] * z[i]; }
        float m = s / D;
        red[0] = m;
        red[1] = rsqrtf(sq / D - m * m + 1e-5f);
    }
    __syncthreads();
    z[t] = (v - red[0]) * red[1] * g[t] + bt[t];
    __syncthreads();
    if (t < 96) {
        float a = b1[t];
        for (int k = 0; k < D; ++k) a += z[k] * W1[k * 96 + t];
        z1[t] = gelu_exact(a);
    }
    __syncthreads();
    if (t < 48) {
        float a = b2[t];
        for (int k = 0; k < 96; ++k) a += z1[k] * W2[k * 48 + t];
        z2[t] = gelu_exact(a);
    }
    __syncthreads();
    if (t < 2) {
        float a = b3[t];
        for (int k = 0; k < 48; ++k) a += z2[k] * W3[k * 2 + t];
        out[(size_t)b * 2 + t] = a;
    }
}

// ---------------- launch ----------------------------------------------------
extern "C" void kernel_launch(void* const* d_in, const int* in_sizes, int n_in,
                              void* d_out, int out_size)
{
    const float* x        = (const float*)d_in[0];
    const float* roi_W    = (const float*)d_in[1];
    const float* roi_b    = (const float*)d_in[2];
    const float* roi_lng  = (const float*)d_in[3];
    const float* roi_lnb  = (const float*)d_in[4];
    const float* pos_emb  = (const float*)d_in[5];
    const float* enc_Wqkv = (const float*)d_in[6];
    const float* enc_bqkv = (const float*)d_in[7];
    const float* enc_Wo   = (const float*)d_in[8];
    const float* enc_bo   = (const float*)d_in[9];
    const float* enc_ln1g = (const float*)d_in[10];
    const float* enc_ln1b = (const float*)d_in[11];
    const float* enc_W1   = (const float*)d_in[12];
    const float* enc_b1   = (const float*)d_in[13];
    const float* enc_W2   = (const float*)d_in[14];
    const float* enc_b2   = (const float*)d_in[15];
    const float* enc_ln2g = (const float*)d_in[16];
    const float* enc_ln2b = (const float*)d_in[17];
    const float* pool_Wqkv= (const float*)d_in[18];
    const float* pool_bqkv= (const float*)d_in[19];
    const float* pool_Wo  = (const float*)d_in[20];
    const float* pool_bo  = (const float*)d_in[21];
    const float* cls_lng  = (const float*)d_in[22];
    const float* cls_lnb  = (const float*)d_in[23];
    const float* cls_W1   = (const float*)d_in[24];
    const float* cls_b1   = (const float*)d_in[25];
    const float* cls_W2   = (const float*)d_in[26];
    const float* cls_b2   = (const float*)d_in[27];
    const float* cls_W3   = (const float*)d_in[28];
    const float* cls_b3   = (const float*)d_in[29];
    float* out = (float*)d_out;

    float *h, *raw, *q, *k, *v, *pool, *pooled;
    hf *xh, *hh, *ah, *fh;
    hf *qbh, *qbl, *kth, *vbh;
    hf *rwh, *qkvh, *woh, *w1h, *w2h, *pwh;
    cudaGetSymbolAddress((void**)&h,    g_h);
    cudaGetSymbolAddress((void**)&raw,  g_raw);
    cudaGetSymbolAddress((void**)&q,    g_q);
    cudaGetSymbolAddress((void**)&k,    g_k);
    cudaGetSymbolAddress((void**)&v,    g_v);
    cudaGetSymbolAddress((void**)&pool, g_pool);
    cudaGetSymbolAddress((void**)&pooled, g_pooled);
    cudaGetSymbolAddress((void**)&xh, g_xh);
    cudaGetSymbolAddress((void**)&hh, g_hh);
    cudaGetSymbolAddress((void**)&ah, g_ah);
    cudaGetSymbolAddress((void**)&fh, g_fh);
    cudaGetSymbolAddress((void**)&qbh, g_qbh); cudaGetSymbolAddress((void**)&qbl, g_qbl);
    cudaGetSymbolAddress((void**)&kth, g_kth);
    cudaGetSymbolAddress((void**)&vbh, g_vbh);
    cudaGetSymbolAddress((void**)&rwh, g_rwh);
    cudaGetSymbolAddress((void**)&qkvh, g_qkvh);
    cudaGetSymbolAddress((void**)&woh, g_woh);
    cudaGetSymbolAddress((void**)&w1h, g_w1h);
    cudaGetSymbolAddress((void**)&w2h, g_w2h);
    cudaGetSymbolAddress((void**)&pwh, g_pwh);

    // ---- pre-convert weights & x (single fp16) ----
    cvt_x_kernel<<<(200 * BATCH * XPAD + 255) / 256, 256>>>(x, xh);
    cvt1_kernel<<<(200 * RD * D + 255) / 256, 256>>>(roi_W, rwh, 200 * RD * D);
    cvt1_kernel<<<(NL * 3 * D * D + 255) / 256, 256>>>(enc_Wqkv, qkvh, NL * 3 * D * D);
    cvt1_kernel<<<(NL * D * D + 255) / 256, 256>>>(enc_Wo, woh, NL * D * D);
    cvt1_kernel<<<(NL * D * FF + 255) / 256, 256>>>(enc_W1, w1h, NL * D * FF);
    cvt1_kernel<<<(NL * FF * D + 255) / 256, 256>>>(enc_W2, w2h, NL * FF * D);
    cvt1_kernel<<<(3 * D * D + 255) / 256, 256>>>(pool_Wqkv, pwh, 3 * D * D);

    // ---- tokenizer ----
    mma_gemm_kernel<<<dim3(2, 3, 200), 256>>>(xh, rwh, roi_b,
        nullptr, nullptr, nullptr, raw, nullptr,
        nullptr, nullptr, nullptr, nullptr, 2, RD, XPAD);
    tok_finish_kernel<<<MTOT / 8, 256>>>(raw, roi_lng, roi_lnb, pos_emb, h, hh);

    // ---- encoder layers ----
    for (int l = 0; l < NL; ++l) {
        mma_gemm_kernel<<<dim3(MTOT / 128, 9, 1), 256>>>(hh,
            qkvh + (size_t)l * 3 * D * D, enc_bqkv + (size_t)l * 3 * D,
            nullptr, nullptr, nullptr, nullptr, nullptr,
            qbh, qbl, kth, vbh, 4, D, D);
        attn_mma_kernel<<<BATCH * NH, 256>>>(qbh, qbl, kth, vbh, ah);
        mma_gemm_kernel<<<dim3(MTOT / 128, 3, 1), 256>>>(ah,
            woh + (size_t)l * D * D, enc_bo + l * D,
            nullptr, nullptr, nullptr, raw, nullptr,
            nullptr, nullptr, nullptr, nullptr, 3, D, D);
        addln_kernel<<<MTOT / 8, 256>>>(raw, h, enc_ln1g + l * D, enc_ln1b + l * D, h, hh);
        mma_gemm_kernel<<<dim3(MTOT / 128, 9, 1), 256>>>(hh,
            w1h + (size_t)l * D * FF, enc_b1 + l * FF,
            nullptr, nullptr, nullptr, nullptr, fh,
            nullptr, nullptr, nullptr, nullptr, 1, D, D);
        mma_gemm_kernel<<<dim3(MTOT / 128, 3, 1), 256>>>(fh,
            w2h + (size_t)l * FF * D, enc_b2 + l * D,
            nullptr, nullptr, nullptr, raw, nullptr,
            nullptr, nullptr, nullptr, nullptr, 3, FF, FF);
        addln_kernel<<<MTOT / 8, 256>>>(raw, h, enc_ln2g + l * D, enc_ln2b + l * D, h, hh);
    }

    // ---- pooling (fp32 QKV path) ----
    mma_gemm_kernel<<<dim3(MTOT / 128, 9, 1), 256>>>(hh, pwh, pool_bqkv,
        q, k, v, nullptr, nullptr,
        nullptr, nullptr, nullptr, nullptr, 0, D, D);
    pool_attn_kernel<<<BATCH * NH, 256>>>(q, k, v, pool);
    pool_proj_kernel<<<BATCH, 192>>>(pool, pool_Wo, pool_bo, pooled);

    // ---- classifier ----
    cls_kernel<<<BATCH, 192>>>(pooled, cls_lng, cls_lnb, cls_W1, cls_b1,
                               cls_W2, cls_b2, cls_W3, cls_b3, out);
}

// round 14
// speedup vs baseline: 1.6579x; 1.0548x over previous
#include <cuda_runtime.h>
#include <cuda_fp16.h>
#include <math.h>

#define BATCH 256
#define S 200
#define D 192
#define NH 6
#define DH 32
#define NL 3
#define FF 576
#define RD 199
#define MTOT (BATCH*S)
#define XPAD 224

typedef __half hf;

// ---------------- mma helpers -----------------------------------------------
__device__ __forceinline__ unsigned smem_u32(const void* p) {
    return (unsigned)__cvta_generic_to_shared(p);
}
__device__ __forceinline__ void ldsm_x4(unsigned addr, unsigned& r0, unsigned& r1,
                                        unsigned& r2, unsigned& r3) {
    asm volatile("ldmatrix.sync.aligned.m8n8.x4.shared.b16 {%0,%1,%2,%3}, [%4];"
                 : "=r"(r0), "=r"(r1), "=r"(r2), "=r"(r3) : "r"(addr));
}
__device__ __forceinline__ void ldsm_x4t(unsigned addr, unsigned& r0, unsigned& r1,
                                         unsigned& r2, unsigned& r3) {
    asm volatile("ldmatrix.sync.aligned.m8n8.x4.trans.shared.b16 {%0,%1,%2,%3}, [%4];"
                 : "=r"(r0), "=r"(r1), "=r"(r2), "=r"(r3) : "r"(addr));
}
__device__ __forceinline__ void mma16816(float c[4], const unsigned a[4], const unsigned b[2]) {
    asm volatile(
        "mma.sync.aligned.m16n8k16.row.col.f32.f16.f16.f32 "
        "{%0,%1,%2,%3}, {%4,%5,%6,%7}, {%8,%9}, {%0,%1,%2,%3};"
        : "+f"(c[0]), "+f"(c[1]), "+f"(c[2]), "+f"(c[3])
        : "r"(a[0]), "r"(a[1]), "r"(a[2]), "r"(a[3]), "r"(b[0]), "r"(b[1]));
}
__device__ __forceinline__ unsigned pack_hf2(hf a, hf b) {
    __half2 t = __halves2half2(a, b);
    return *(unsigned*)&t;
}

// ---------------- scratch (device globals) ---------------------------------
__device__ float g_h[MTOT*D];
__device__ float g_raw[MTOT*D];
__device__ float g_q[MTOT*D];
__device__ float g_k[MTOT*D];
__device__ float g_v[MTOT*D];
__device__ float g_pool[BATCH*D];
__device__ float g_pooled[BATCH*D];

// fp16 activation buffers
__device__ hf g_xh[200*BATCH*XPAD];
__device__ hf g_hh[MTOT*D];
__device__ hf g_ah[MTOT*D];
__device__ hf g_fh[MTOT*FF];
// attention operands: all single fp16
__device__ hf g_qbh[MTOT*D];                  // [bh][s][dh] (pre-scaled)
__device__ hf g_kth[MTOT*D];                  // [bh][dh][s]
__device__ hf g_vbh[MTOT*D];                  // [bh][s][dh]
// single-fp16 weight buffers
__device__ hf g_rwh[200*RD*D];
__device__ hf g_qkvh[NL*3*D*D];
__device__ hf g_woh[NL*D*D];
__device__ hf g_w1h[NL*D*FF];
__device__ hf g_w2h[NL*FF*D];
__device__ hf g_pwh[3*D*D];

__device__ __forceinline__ float gelu_exact(float x) {
    return 0.5f * x * (1.0f + erff(x * 0.70710678118654752f));
}

// ---------------- conversion kernels ----------------------------------------
__global__ void cvt1_kernel(const float* __restrict__ in, hf* __restrict__ o, int n)
{
    int i = blockIdx.x * 256 + threadIdx.x;
    if (i < n) o[i] = __float2half(in[i]);
}
__global__ void cvt_x_kernel(const float* __restrict__ x, hf* __restrict__ hi)
{
    int i = blockIdx.x * 256 + threadIdx.x;
    if (i >= 200 * BATCH * XPAD) return;
    int k = i % XPAD; int tmp = i / XPAD;
    int b = tmp % BATCH; int roi = tmp / BATCH;
    float v = (k < RD) ? x[(size_t)b * (200 * RD) + roi * RD + k] : 0.f;
    hi[i] = __float2half(v);
}

// ============================================================================
// Tensor-core GEMM, fp16 x fp16 (1 MMA/k16), register-prefetch double buffer.
// BM=128, BN=64, BK=32, 256 thr.
// mode 0: QKV fp32 scatter (pool); mode 1: FFN1 (+GELU) -> hf;
// mode 2: tokenizer raw fp32; mode 3: raw fp32 C; mode 4: QKV hf scatter + K^T.
// ============================================================================
__global__ __launch_bounds__(256) void mma_gemm_kernel(
    const hf* __restrict__ Ah,
    const hf* __restrict__ Wh,
    const float* __restrict__ bias,
    float* __restrict__ oq, float* __restrict__ ok, float* __restrict__ ov,
    float* __restrict__ of, hf* __restrict__ obh,
    hf* __restrict__ xqh, hf* __restrict__ xkh, hf* __restrict__ xvh,
    int mode, int K, int lda)
{
    __shared__ hf AsH[128][40];
    __shared__ hf BsH[32][72];

    int m0 = blockIdx.x * 128, n0 = blockIdx.y * 64, roi = blockIdx.z;
    int t = threadIdx.x;
    int warp = t >> 5, lane = t & 31;
    int wm = warp >> 1, wn = warp & 1;

    const hf* Bph; int ldb, nb;
    if (mode == 0 || mode == 4) {
        int wh = n0 / D;
        Bph = Wh + (size_t)wh * D * D;
        nb = n0 - wh * D; ldb = D;
    } else if (mode == 1) { Bph = Wh; nb = n0; ldb = FF; }
    else if (mode == 2) { Bph = Wh + (size_t)roi * RD * D; nb = n0; ldb = D; }
    else                { Bph = Wh; nb = n0; ldb = D; }

    if (mode == 2) Ah += (size_t)roi * BATCH * XPAD;

    float acc[2][4][4] = {};

    // ---- preload tile 0 ----
#pragma unroll
    for (int p = t; p < 1024; p += 256) {
        int row = p >> 3, c4 = (p & 7) * 4;
        *(uint2*)&AsH[row][c4] = *(const uint2*)(Ah + (size_t)(m0 + row) * lda + c4);
    }
#pragma unroll
    for (int p = t; p < 512; p += 256) {
        int k = p >> 4, n4 = (p & 15) * 4;
        uint2 zh = make_uint2(0u, 0u);
        if (k < K) zh = *(const uint2*)(Bph + (size_t)k * ldb + nb + n4);
        *(uint2*)&BsH[k][n4] = zh;
    }
    __syncthreads();

    for (int k0 = 0; k0 < K; k0 += 32) {
        bool has_next = (k0 + 32 < K);
        uint2 pa[4], pb[2];
        if (has_next) {
            int kn = k0 + 32;
#pragma unroll
            for (int i = 0; i < 4; ++i) {
                int p = t + i * 256;
                int row = p >> 3, c4 = (p & 7) * 4;
                pa[i] = *(const uint2*)(Ah + (size_t)(m0 + row) * lda + kn + c4);
            }
#pragma unroll
            for (int i = 0; i < 2; ++i) {
                int p = t + i * 256;
                int k = p >> 4, n4 = (p & 15) * 4;
                uint2 zh = make_uint2(0u, 0u);
                if (kn + k < K) zh = *(const uint2*)(Bph + (size_t)(kn + k) * ldb + nb + n4);
                pb[i] = zh;
            }
        }

#pragma unroll
        for (int ks = 0; ks < 2; ++ks) {
            int kb = ks * 16;
            unsigned aH[2][4];
            int aro = ((lane >> 3) & 1) * 8 + (lane & 7);
            int aco = kb + (lane >> 4) * 8;
#pragma unroll
            for (int mt = 0; mt < 2; ++mt) {
                int r = wm * 32 + mt * 16 + aro;
                ldsm_x4(smem_u32(&AsH[r][aco]), aH[mt][0], aH[mt][1], aH[mt][2], aH[mt][3]);
            }
            unsigned bH[4][2];
            int bro = kb + ((lane >> 3) & 1) * 8 + (lane & 7);
            int bco = wn * 32 + (lane >> 4) * 8;
#pragma unroll
            for (int np = 0; np < 2; ++np) {
                unsigned r0, r1, r2, r3;
                ldsm_x4t(smem_u32(&BsH[bro][bco + np * 16]), r0, r1, r2, r3);
                bH[np*2][0] = r0; bH[np*2][1] = r1; bH[np*2+1][0] = r2; bH[np*2+1][1] = r3;
            }
#pragma unroll
            for (int mt = 0; mt < 2; ++mt)
#pragma unroll
                for (int nt = 0; nt < 4; ++nt)
                    mma16816(acc[mt][nt], aH[mt], bH[nt]);
        }

        if (has_next) {
            __syncthreads();
#pragma unroll
            for (int i = 0; i < 4; ++i) {
                int p = t + i * 256;
                int row = p >> 3, c4 = (p & 7) * 4;
                *(uint2*)&AsH[row][c4] = pa[i];
            }
#pragma unroll
            for (int i = 0; i < 2; ++i) {
                int p = t + i * 256;
                int k = p >> 4, n4 = (p & 15) * 4;
                *(uint2*)&BsH[k][n4] = pb[i];
            }
            __syncthreads();
        }
    }

    // ---- epilogue ----
    int g = lane >> 2, tq = (lane & 3) * 2;
#pragma unroll
    for (int mt = 0; mt < 2; ++mt) {
        int r0 = m0 + wm * 32 + mt * 16 + g;
#pragma unroll
        for (int nt = 0; nt < 4; ++nt) {
            float* c = acc[mt][nt];
            if (mode == 0) {
                int wh = n0 / D;
                int colq = nb + wn * 32 + nt * 8 + tq;
                int hd = colq >> 5, dh = colq & 31;
                float2 bb = *(const float2*)(bias + wh * D + colq);
                float* o = (wh == 0) ? oq : ((wh == 1) ? ok : ov);
                int m = r0;
                int b = m / S, s = m - b * S;
                *(float2*)(o + (((size_t)b * NH + hd) * S + s) * DH + dh)
                    = make_float2(c[0] + bb.x, c[1] + bb.y);
                m = r0 + 8; b = m / S; s = m - b * S;
                *(float2*)(o + (((size_t)b * NH + hd) * S + s) * DH + dh)
                    = make_float2(c[2] + bb.x, c[3] + bb.y);
            } else if (mode == 4) {
                int wh = n0 / D;
                int colq = nb + wn * 32 + nt * 8 + tq;
                int hd = colq >> 5, dh = colq & 31;
                float2 bb = *(const float2*)(bias + wh * D + colq);
#pragma unroll
                for (int rr = 0; rr < 2; ++rr) {
                    int m = r0 + rr * 8;
                    int b = m / S, s = m - b * S;
                    int bhq = b * NH + hd;
                    float f0 = c[rr * 2 + 0] + bb.x;
                    float f1 = c[rr * 2 + 1] + bb.y;
                    if (wh == 0) {
                        f0 *= 0.17677669529663687f; f1 *= 0.17677669529663687f;
                        size_t off = ((size_t)bhq * S + s) * DH + dh;
                        *(unsigned*)(xqh + off)
                            = pack_hf2(__float2half(f0), __float2half(f1));
                    } else if (wh == 1) {
                        size_t off = ((size_t)bhq * DH + dh) * S + s;
                        xkh[off]     = __float2half(f0);
                        xkh[off + S] = __float2half(f1);
                    } else {
                        size_t off = ((size_t)bhq * S + s) * DH + dh;
                        *(unsigned*)(xvh + off)
                            = pack_hf2(__float2half(f0), __float2half(f1));
                    }
                }
            } else if (mode == 1) {
                int col = n0 + wn * 32 + nt * 8 + tq;
                float2 bb = *(const float2*)(bias + col);
                float f0 = gelu_exact(c[0] + bb.x), f1 = gelu_exact(c[1] + bb.y);
                *(unsigned*)(obh + (size_t)r0 * FF + col)
                    = pack_hf2(__float2half(f0), __float2half(f1));
                f0 = gelu_exact(c[2] + bb.x); f1 = gelu_exact(c[3] + bb.y);
                *(unsigned*)(obh + (size_t)(r0 + 8) * FF + col)
                    = pack_hf2(__float2half(f0), __float2half(f1));
            } else if (mode == 2) {
                int col = n0 + wn * 32 + nt * 8 + tq;
                float2 bb = *(const float2*)(bias + (size_t)roi * D + col);
                *(float2*)(of + ((size_t)r0 * S + roi) * D + col)
                    = make_float2(c[0] + bb.x, c[1] + bb.y);
                *(float2*)(of + ((size_t)(r0 + 8) * S + roi) * D + col)
                    = make_float2(c[2] + bb.x, c[3] + bb.y);
            } else {
                int col = n0 + wn * 32 + nt * 8 + tq;
                float2 bb = *(const float2*)(bias + col);
                *(float2*)(of + (size_t)r0 * D + col)
                    = make_float2(c[0] + bb.x, c[1] + bb.y);
                *(float2*)(of + (size_t)(r0 + 8) * D + col)
                    = make_float2(c[2] + bb.x, c[3] + bb.y);
            }
        }
    }
}

// ============================================================================
// Tensor-core attention: all single fp16 (Q, K, V, P); 1 MMA/k16.
// CTA per (b,h), 8 warps, queries padded to 208, keys in 32-key tiles,
// register-prefetch K/V double buffer.
// ============================================================================
__global__ __launch_bounds__(256, 2) void attn_mma_kernel(
    const hf* __restrict__ qbh,
    const hf* __restrict__ kth, const hf* __restrict__ vbh,
    hf* __restrict__ oh)
{
    __shared__ hf Qh[208][40];
    __shared__ hf Kh[32][40];
    __shared__ hf Vh[32][40];

    int bh = blockIdx.x;
    int b = bh / NH, hd = bh - b * NH;
    int t = threadIdx.x, warp = t >> 5, lane = t & 31;
    int g = lane >> 2, tq = lane & 3;

    const hf* khb = kth + (size_t)bh * DH * S;
    const unsigned* vhp = (const unsigned*)(vbh + (size_t)bh * S * DH);
    const unsigned* qhp = (const unsigned*)(qbh + (size_t)bh * S * DH);

    for (int i = t; i < 208 * 16; i += 256) {
        int row = i >> 4, cp = i & 15;
        unsigned a = 0;
        if (row < S) a = qhp[row * 16 + cp];
        *(unsigned*)&Qh[row][cp * 2] = a;
    }
#pragma unroll
    for (int i = t; i < 512; i += 256) {
        int row = i >> 4, cp = i & 15;
        *(unsigned*)&Kh[row][cp * 2] = *(const unsigned*)(khb + row * S + cp * 2);
        *(unsigned*)&Vh[row][cp * 2] = vhp[row * 16 + cp];
    }
    __syncthreads();

    int nmt = (warp < 5) ? 2 : 1;
    int mt0 = warp * 16, mt1 = (8 + warp) * 16;
    int aro  = ((lane >> 3) & 1) * 8 + (lane & 7);
    int acoh = (lane >> 4) * 8;

    unsigned qH[2][2][4];
    for (int mi = 0; mi < nmt; ++mi) {
        int mrow = mi ? mt1 : mt0;
#pragma unroll
        for (int ks = 0; ks < 2; ++ks)
            ldsm_x4(smem_u32(&Qh[mrow + aro][ks * 16 + acoh]),
                    qH[mi][ks][0], qH[mi][ks][1], qH[mi][ks][2], qH[mi][ks][3]);
    }

    float oacc[2][4][4] = {};
    float lsum[2][2] = {};

    for (int kt = 0; kt < 7; ++kt) {
        bool has_next = (kt < 6);
        unsigned pk[2], pv[2];
        if (has_next) {
            int kn0 = (kt + 1) * 32;
#pragma unroll
            for (int i = 0; i < 2; ++i) {
                int p = t + i * 256;
                int row = p >> 4, cp = p & 15;
                int key = kn0 + cp * 2;
                unsigned a = 0;
                if (key < S) a = *(const unsigned*)(khb + row * S + key);
                pk[i] = a;
                int keyv = kn0 + row;
                unsigned av = 0;
                if (keyv < S) av = vhp[keyv * 16 + cp];
                pv[i] = av;
            }
        }

        int kt0 = kt * 32;
        for (int mi = 0; mi < nmt; ++mi) {
#pragma unroll
            for (int kg = 0; kg < 2; ++kg) {
                float sc2[2][4] = {};
#pragma unroll
                for (int ks = 0; ks < 2; ++ks) {
                    unsigned kh2[2][2], r0, r1, r2, r3;
                    ldsm_x4t(smem_u32(&Kh[ks * 16 + aro][kg * 16 + acoh]), r0, r1, r2, r3);
                    kh2[0][0] = r0; kh2[0][1] = r1; kh2[1][0] = r2; kh2[1][1] = r3;
#pragma unroll
                    for (int j = 0; j < 2; ++j)
                        mma16816(sc2[j], qH[mi][ks], kh2[j]);
                }
                float e[8];
#pragma unroll
                for (int j = 0; j < 2; ++j) {
                    int keyb = kt0 + (kg * 2 + j) * 8 + tq * 2;
                    float e0 = __expf(sc2[j][0]);
                    float e1 = __expf(sc2[j][1]);
                    float e2 = __expf(sc2[j][2]);
                    float e3 = __expf(sc2[j][3]);
                    if (keyb >= S)     { e0 = 0.f; e2 = 0.f; }
                    if (keyb + 1 >= S) { e1 = 0.f; e3 = 0.f; }
                    lsum[mi][0] += e0 + e1;
                    lsum[mi][1] += e2 + e3;
                    e[j * 4 + 0] = e0; e[j * 4 + 1] = e1;
                    e[j * 4 + 2] = e2; e[j * 4 + 3] = e3;
                }
                unsigned paH[4];
                paH[0] = pack_hf2(__float2half(e[0]), __float2half(e[1]));
                paH[1] = pack_hf2(__float2half(e[2]), __float2half(e[3]));
                paH[2] = pack_hf2(__float2half(e[4]), __float2half(e[5]));
                paH[3] = pack_hf2(__float2half(e[6]), __float2half(e[7]));
#pragma unroll
                for (int np = 0; np < 2; ++np) {
                    unsigned vh2[2][2], r0, r1, r2, r3;
                    ldsm_x4t(smem_u32(&Vh[kg * 16 + aro][np * 16 + acoh]), r0, r1, r2, r3);
                    vh2[0][0] = r0; vh2[0][1] = r1; vh2[1][0] = r2; vh2[1][1] = r3;
#pragma unroll
                    for (int j = 0; j < 2; ++j)
                        mma16816(oacc[mi][np * 2 + j], paH, vh2[j]);
                }
            }
        }

        if (has_next) {
            __syncthreads();
#pragma unroll
            for (int i = 0; i < 2; ++i) {
                int p = t + i * 256;
                int row = p >> 4, cp = p & 15;
                *(unsigned*)&Kh[row][cp * 2] = pk[i];
                *(unsigned*)&Vh[row][cp * 2] = pv[i];
            }
            __syncthreads();
        }
    }

    for (int mi = 0; mi < nmt; ++mi) {
        float l0 = lsum[mi][0], l1 = lsum[mi][1];
        l0 += __shfl_xor_sync(0xffffffffu, l0, 1);
        l0 += __shfl_xor_sync(0xffffffffu, l0, 2);
        l1 += __shfl_xor_sync(0xffffffffu, l1, 1);
        l1 += __shfl_xor_sync(0xffffffffu, l1, 2);
        float i0 = 1.f / l0, i1 = 1.f / l1;
        int mrow = mi ? mt1 : mt0;
        int s0 = mrow + g;
#pragma unroll
        for (int n8 = 0; n8 < 4; ++n8) {
            int col = hd * DH + n8 * 8 + tq * 2;
            if (s0 < S) {
                float u0 = oacc[mi][n8][0] * i0, u1 = oacc[mi][n8][1] * i0;
                size_t off = ((size_t)b * S + s0) * D + col;
                *(unsigned*)(oh + off) = pack_hf2(__float2half(u0), __float2half(u1));
            }
            if (s0 + 8 < S) {
                float u0 = oacc[mi][n8][2] * i1, u1 = oacc[mi][n8][3] * i1;
                size_t off = ((size_t)b * S + s0 + 8) * D + col;
                *(unsigned*)(oh + off) = pack_hf2(__float2half(u0), __float2half(u1));
            }
        }
    }
}

// ============================================================================
// add + LayerNorm: out = LN(raw + res) -> fp32 h + fp16
// ============================================================================
__global__ void addln_kernel(const float* __restrict__ raw,
                             const float* __restrict__ res,
                             const float* __restrict__ lng,
                             const float* __restrict__ lnb,
                             float* __restrict__ out,
                             hf* __restrict__ oh)
{
    int row = blockIdx.x * 8 + (threadIdx.x >> 5);
    int lane = threadIdx.x & 31;
    float vv[6];
    float sum = 0.f, sq = 0.f;
#pragma unroll
    for (int j = 0; j < 6; ++j) {
        int c = lane + 32 * j;
        vv[j] = raw[(size_t)row * D + c] + res[(size_t)row * D + c];
        sum += vv[j]; sq += vv[j] * vv[j];
    }
#pragma unroll
    for (int o = 16; o > 0; o >>= 1) {
        sum += __shfl_xor_sync(0xffffffffu, sum, o);
        sq  += __shfl_xor_sync(0xffffffffu, sq,  o);
    }
    float mean = sum * (1.f / D);
    float rstd = rsqrtf(sq * (1.f / D) - mean * mean + 1e-5f);
#pragma unroll
    for (int j = 0; j < 6; ++j) {
        int c = lane + 32 * j;
        float val = (vv[j] - mean) * rstd * lng[c] + lnb[c];
        out[(size_t)row * D + c] = val;
        oh[(size_t)row * D + c] = __float2half(val);
    }
}

// ============================================================================
// token epilogue: per-roi LN + GELU + pos -> fp32 h + fp16
// ============================================================================
__global__ void tok_finish_kernel(const float* __restrict__ raw,
                                  const float* __restrict__ lng,
                                  const float* __restrict__ lnb,
                                  const float* __restrict__ pos,
                                  float* __restrict__ out,
                                  hf* __restrict__ oh)
{
    int row = blockIdx.x * 8 + (threadIdx.x >> 5);
    int roi = row % S;
    int lane = threadIdx.x & 31;
    float vv[6];
    float sum = 0.f, sq = 0.f;
#pragma unroll
    for (int j = 0; j < 6; ++j) {
        vv[j] = raw[(size_t)row * D + lane + 32 * j];
        sum += vv[j]; sq += vv[j] * vv[j];
    }
#pragma unroll
    for (int o = 16; o > 0; o >>= 1) {
        sum += __shfl_xor_sync(0xffffffffu, sum, o);
        sq  += __shfl_xor_sync(0xffffffffu, sq,  o);
    }
    float mean = sum * (1.f / D);
    float rstd = rsqrtf(sq * (1.f / D) - mean * mean + 1e-5f);
#pragma unroll
    for (int j = 0; j < 6; ++j) {
        int c = lane + 32 * j;
        float v = (vv[j] - mean) * rstd * lng[(size_t)roi * D + c] + lnb[(size_t)roi * D + c];
        float val = gelu_exact(v) + pos[(size_t)roi * D + c];
        out[(size_t)row * D + c] = val;
        oh[(size_t)row * D + c] = __float2half(val);
    }
}

// ---------------- pooled attention (Q=1 via linearity) ---------------------
__global__ void pool_attn_kernel(const float* __restrict__ q,
                                 const float* __restrict__ k,
                                 const float* __restrict__ v,
                                 float* __restrict__ out)
{
    __shared__ float qm[DH];
    __shared__ float sc[S];
    __shared__ float red[2];
    int bh = blockIdx.x;
    int b = bh / NH, hd = bh % NH;
    size_t base = (size_t)bh * S * DH;
    int t = threadIdx.x;
    if (t < DH) {
        float s = 0.f;
        for (int j = 0; j < S; ++j) s += q[base + j * DH + t];
        qm[t] = s * (1.f / S) * 0.17677669529663687f;
    }
    __syncthreads();
    if (t < S) {
        float x = 0.f;
#pragma unroll
        for (int i = 0; i < DH; ++i) x += qm[i] * k[base + t * DH + i];
        sc[t] = x;
    }
    __syncthreads();
    if (t == 0) {
        float mx = -1e30f;
        for (int s = 0; s < S; ++s) mx = fmaxf(mx, sc[s]);
        red[0] = mx;
    }
    __syncthreads();
    if (t < S) sc[t] = __expf(sc[t] - red[0]);
    __syncthreads();
    if (t == 0) {
        float l = 0.f;
        for (int s = 0; s < S; ++s) l += sc[s];
        red[1] = 1.f / l;
    }
    __syncthreads();
    if (t < DH) {
        float o = 0.f;
        for (int s = 0; s < S; ++s) o += sc[s] * v[base + s * DH + t];
        out[(size_t)b * D + hd * DH + t] = o * red[1];
    }
}

// ---------------- pooled projection ----------------------------------------
__global__ void pool_proj_kernel(const float* __restrict__ in,
                                 const float* __restrict__ W,
                                 const float* __restrict__ bias,
                                 float* __restrict__ out)
{
    __shared__ float row[D];
    int b = blockIdx.x, d = threadIdx.x;
    row[d] = in[(size_t)b * D + d];
    __syncthreads();
    float s = bias[d];
    for (int k = 0; k < D; ++k) s += row[k] * W[(size_t)k * D + d];
    out[(size_t)b * D + d] = s;
}

// ---------------- classifier head ------------------------------------------
__global__ void cls_kernel(const float* __restrict__ in,
                           const float* __restrict__ g,  const float* __restrict__ bt,
                           const float* __restrict__ W1, const float* __restrict__ b1,
                           const float* __restrict__ W2, const float* __restrict__ b2,
                           const float* __restrict__ W3, const float* __restrict__ b3,
                           float* __restrict__ out)
{
    __shared__ float z[D];
    __shared__ float z1[96];
    __shared__ float z2[48];
    __shared__ float red[2];
    int b = blockIdx.x, t = threadIdx.x;
    float v = in[(size_t)b * D + t];
    z[t] = v;
    __syncthreads();
    if (t == 0) {
        float s = 0.f, sq = 0.f;
        for (int i = 0; i < D; ++i) { s += z[i]; sq += z[i] * z[i]; }
        float m = s / D;
        red[0] = m;
        red[1] = rsqrtf(sq / D - m * m + 1e-5f);
    }
    __syncthreads();
    z[t] = (v - red[0]) * red[1] * g[t] + bt[t];
    __syncthreads();
    if (t < 96) {
        float a = b1[t];
        for (int k = 0; k < D; ++k) a += z[k] * W1[k * 96 + t];
        z1[t] = gelu_exact(a);
    }
    __syncthreads();
    if (t < 48) {
        float a = b2[t];
        for (int k = 0; k < 96; ++k) a += z1[k] * W2[k * 48 + t];
        z2[t] = gelu_exact(a);
    }
    __syncthreads();
    if (t < 2) {
        float a = b3[t];
        for (int k = 0; k < 48; ++k) a += z2[k] * W3[k * 2 + t];
        out[(size_t)b * 2 + t] = a;
    }
}

// ---------------- launch ----------------------------------------------------
extern "C" void kernel_launch(void* const* d_in, const int* in_sizes, int n_in,
                              void* d_out, int out_size)
{
    const float* x        = (const float*)d_in[0];
    const float* roi_W    = (const float*)d_in[1];
    const float* roi_b    = (const float*)d_in[2];
    const float* roi_lng  = (const float*)d_in[3];
    const float* roi_lnb  = (const float*)d_in[4];
    const float* pos_emb  = (const float*)d_in[5];
    const float* enc_Wqkv = (const float*)d_in[6];
    const float* enc_bqkv = (const float*)d_in[7];
    const float* enc_Wo   = (const float*)d_in[8];
    const float* enc_bo   = (const float*)d_in[9];
    const float* enc_ln1g = (const float*)d_in[10];
    const float* enc_ln1b = (const float*)d_in[11];
    const float* enc_W1   = (const float*)d_in[12];
    const float* enc_b1   = (const float*)d_in[13];
    const float* enc_W2   = (const float*)d_in[14];
    const float* enc_b2   = (const float*)d_in[15];
    const float* enc_ln2g = (const float*)d_in[16];
    const float* enc_ln2b = (const float*)d_in[17];
    const float* pool_Wqkv= (const float*)d_in[18];
    const float* pool_bqkv= (const float*)d_in[19];
    const float* pool_Wo  = (const float*)d_in[20];
    const float* pool_bo  = (const float*)d_in[21];
    const float* cls_lng  = (const float*)d_in[22];
    const float* cls_lnb  = (const float*)d_in[23];
    const float* cls_W1   = (const float*)d_in[24];
    const float* cls_b1   = (const float*)d_in[25];
    const float* cls_W2   = (const float*)d_in[26];
    const float* cls_b2   = (const float*)d_in[27];
    const float* cls_W3   = (const float*)d_in[28];
    const float* cls_b3   = (const float*)d_in[29];
    float* out = (float*)d_out;

    float *h, *raw, *q, *k, *v, *pool, *pooled;
    hf *xh, *hh, *ah, *fh;
    hf *qbh, *kth, *vbh;
    hf *rwh, *qkvh, *woh, *w1h, *w2h, *pwh;
    cudaGetSymbolAddress((void**)&h,    g_h);
    cudaGetSymbolAddress((void**)&raw,  g_raw);
    cudaGetSymbolAddress((void**)&q,    g_q);
    cudaGetSymbolAddress((void**)&k,    g_k);
    cudaGetSymbolAddress((void**)&v,    g_v);
    cudaGetSymbolAddress((void**)&pool, g_pool);
    cudaGetSymbolAddress((void**)&pooled, g_pooled);
    cudaGetSymbolAddress((void**)&xh, g_xh);
    cudaGetSymbolAddress((void**)&hh, g_hh);
    cudaGetSymbolAddress((void**)&ah, g_ah);
    cudaGetSymbolAddress((void**)&fh, g_fh);
    cudaGetSymbolAddress((void**)&qbh, g_qbh);
    cudaGetSymbolAddress((void**)&kth, g_kth);
    cudaGetSymbolAddress((void**)&vbh, g_vbh);
    cudaGetSymbolAddress((void**)&rwh, g_rwh);
    cudaGetSymbolAddress((void**)&qkvh, g_qkvh);
    cudaGetSymbolAddress((void**)&woh, g_woh);
    cudaGetSymbolAddress((void**)&w1h, g_w1h);
    cudaGetSymbolAddress((void**)&w2h, g_w2h);
    cudaGetSymbolAddress((void**)&pwh, g_pwh);

    // ---- pre-convert weights & x (single fp16) ----
    cvt_x_kernel<<<(200 * BATCH * XPAD + 255) / 256, 256>>>(x, xh);
    cvt1_kernel<<<(200 * RD * D + 255) / 256, 256>>>(roi_W, rwh, 200 * RD * D);
    cvt1_kernel<<<(NL * 3 * D * D + 255) / 256, 256>>>(enc_Wqkv, qkvh, NL * 3 * D * D);
    cvt1_kernel<<<(NL * D * D + 255) / 256, 256>>>(enc_Wo, woh, NL * D * D);
    cvt1_kernel<<<(NL * D * FF + 255) / 256, 256>>>(enc_W1, w1h, NL * D * FF);
    cvt1_kernel<<<(NL * FF * D + 255) / 256, 256>>>(enc_W2, w2h, NL * FF * D);
    cvt1_kernel<<<(3 * D * D + 255) / 256, 256>>>(pool_Wqkv, pwh, 3 * D * D);

    // ---- tokenizer ----
    mma_gemm_kernel<<<dim3(2, 3, 200), 256>>>(xh, rwh, roi_b,
        nullptr, nullptr, nullptr, raw, nullptr,
        nullptr, nullptr, nullptr, 2, RD, XPAD);
    tok_finish_kernel<<<MTOT / 8, 256>>>(raw, roi_lng, roi_lnb, pos_emb, h, hh);

    // ---- encoder layers ----
    for (int l = 0; l < NL; ++l) {
        mma_gemm_kernel<<<dim3(MTOT / 128, 9, 1), 256>>>(hh,
            qkvh + (size_t)l * 3 * D * D, enc_bqkv + (size_t)l * 3 * D,
            nullptr, nullptr, nullptr, nullptr, nullptr,
            qbh, kth, vbh, 4, D, D);
        attn_mma_kernel<<<BATCH * NH, 256>>>(qbh, kth, vbh, ah);
        mma_gemm_kernel<<<dim3(MTOT / 128, 3, 1), 256>>>(ah,
            woh + (size_t)l * D * D, enc_bo + l * D,
            nullptr, nullptr, nullptr, raw, nullptr,
            nullptr, nullptr, nullptr, 3, D, D);
        addln_kernel<<<MTOT / 8, 256>>>(raw, h, enc_ln1g + l * D, enc_ln1b + l * D, h, hh);
        mma_gemm_kernel<<<dim3(MTOT / 128, 9, 1), 256>>>(hh,
            w1h + (size_t)l * D * FF, enc_b1 + l * FF,
            nullptr, nullptr, nullptr, nullptr, fh,
            nullptr, nullptr, nullptr, 1, D, D);
        mma_gemm_kernel<<<dim3(MTOT / 128, 3, 1), 256>>>(fh,
            w2h + (size_t)l * FF * D, enc_b2 + l * D,
            nullptr, nullptr, nullptr, raw, nullptr,
            nullptr, nullptr, nullptr, 3, FF, FF);
        addln_kernel<<<MTOT / 8, 256>>>(raw, h, enc_ln2g + l * D, enc_ln2b + l * D, h, hh);
    }

    // ---- pooling (fp32 QKV path) ----
    mma_gemm_kernel<<<dim3(MTOT / 128, 9, 1), 256>>>(hh, pwh, pool_bqkv,
        q, k, v, nullptr, nullptr,
        nullptr, nullptr, nullptr, 0, D, D);
    pool_attn_kernel<<<BATCH * NH, 256>>>(q, k, v, pool);
    pool_proj_kernel<<<BATCH, 192>>>(pool, pool_Wo, pool_bo, pooled);

    // ---- classifier ----
    cls_kernel<<<BATCH, 192>>>(pooled, cls_lng, cls_lnb, cls_W1, cls_b1,
                               cls_W2, cls_b2, cls_W3, cls_b3, out);
}

// round 15
// speedup vs baseline: 1.7238x; 1.0397x over previous
#include <cuda_runtime.h>
#include <cuda_fp16.h>
#include <math.h>

#define BATCH 256
#define S 200
#define D 192
#define NH 6
#define DH 32
#define NL 3
#define FF 576
#define RD 199
#define MTOT (BATCH*S)
#define XPAD 224

typedef __half hf;

// ---------------- mma helpers -----------------------------------------------
__device__ __forceinline__ unsigned smem_u32(const void* p) {
    return (unsigned)__cvta_generic_to_shared(p);
}
__device__ __forceinline__ void ldsm_x4(unsigned addr, unsigned& r0, unsigned& r1,
                                        unsigned& r2, unsigned& r3) {
    asm volatile("ldmatrix.sync.aligned.m8n8.x4.shared.b16 {%0,%1,%2,%3}, [%4];"
                 : "=r"(r0), "=r"(r1), "=r"(r2), "=r"(r3) : "r"(addr));
}
__device__ __forceinline__ void ldsm_x4t(unsigned addr, unsigned& r0, unsigned& r1,
                                         unsigned& r2, unsigned& r3) {
    asm volatile("ldmatrix.sync.aligned.m8n8.x4.trans.shared.b16 {%0,%1,%2,%3}, [%4];"
                 : "=r"(r0), "=r"(r1), "=r"(r2), "=r"(r3) : "r"(addr));
}
__device__ __forceinline__ void mma16816(float c[4], const unsigned a[4], const unsigned b[2]) {
    asm volatile(
        "mma.sync.aligned.m16n8k16.row.col.f32.f16.f16.f32 "
        "{%0,%1,%2,%3}, {%4,%5,%6,%7}, {%8,%9}, {%0,%1,%2,%3};"
        : "+f"(c[0]), "+f"(c[1]), "+f"(c[2]), "+f"(c[3])
        : "r"(a[0]), "r"(a[1]), "r"(a[2]), "r"(a[3]), "r"(b[0]), "r"(b[1]));
}
__device__ __forceinline__ unsigned pack_hf2(hf a, hf b) {
    __half2 t = __halves2half2(a, b);
    return *(unsigned*)&t;
}

// ---------------- scratch (device globals) ---------------------------------
__device__ float g_q[MTOT*D];
__device__ float g_k[MTOT*D];
__device__ float g_v[MTOT*D];
__device__ float g_pool[BATCH*D];
__device__ float g_pooled[BATCH*D];

// fp16 activation buffers (residual stream lives in g_hh only)
__device__ hf g_xh[200*BATCH*XPAD];
__device__ hf g_raw16[MTOT*D];
__device__ hf g_hh[MTOT*D];
__device__ hf g_ah[MTOT*D];
__device__ hf g_fh[MTOT*FF];
// attention operands
__device__ hf g_qbh[MTOT*D];                  // [bh][s][dh] (pre-scaled)
__device__ hf g_kth[MTOT*D];                  // [bh][dh][s]
__device__ hf g_vbh[MTOT*D];                  // [bh][s][dh]
// single-fp16 weight buffers
__device__ hf g_rwh[200*RD*D];
__device__ hf g_qkvh[NL*3*D*D];
__device__ hf g_woh[NL*D*D];
__device__ hf g_w1h[NL*D*FF];
__device__ hf g_w2h[NL*FF*D];
__device__ hf g_pwh[3*D*D];

__device__ __forceinline__ float gelu_exact(float x) {
    return 0.5f * x * (1.0f + erff(x * 0.70710678118654752f));
}

// ---------------- conversion kernels ----------------------------------------
__global__ void cvt1_kernel(const float* __restrict__ in, hf* __restrict__ o, int n)
{
    int i = blockIdx.x * 256 + threadIdx.x;
    if (i < n) o[i] = __float2half(in[i]);
}
__global__ void cvt_x_kernel(const float* __restrict__ x, hf* __restrict__ hi)
{
    int i = blockIdx.x * 256 + threadIdx.x;
    if (i >= 200 * BATCH * XPAD) return;
    int k = i % XPAD; int tmp = i / XPAD;
    int b = tmp % BATCH; int roi = tmp / BATCH;
    float v = (k < RD) ? x[(size_t)b * (200 * RD) + roi * RD + k] : 0.f;
    hi[i] = __float2half(v);
}

// ============================================================================
// Tensor-core GEMM, fp16 x fp16 (1 MMA/k16), register-prefetch double buffer.
// BM=128, BN=64, BK=32, 256 thr.
// mode 0: QKV fp32 scatter (pool); mode 1: FFN1 (+GELU) -> hf;
// mode 2: tokenizer raw fp16 scatter; mode 3: raw fp16; mode 4: QKV hf + K^T.
// ============================================================================
__global__ __launch_bounds__(256) void mma_gemm_kernel(
    const hf* __restrict__ Ah,
    const hf* __restrict__ Wh,
    const float* __restrict__ bias,
    float* __restrict__ oq, float* __restrict__ ok, float* __restrict__ ov,
    hf* __restrict__ ofh,
    hf* __restrict__ xqh, hf* __restrict__ xkh, hf* __restrict__ xvh,
    int mode, int K, int lda)
{
    __shared__ hf AsH[128][40];
    __shared__ hf BsH[32][72];

    int m0 = blockIdx.x * 128, n0 = blockIdx.y * 64, roi = blockIdx.z;
    int t = threadIdx.x;
    int warp = t >> 5, lane = t & 31;
    int wm = warp >> 1, wn = warp & 1;

    const hf* Bph; int ldb, nb;
    if (mode == 0 || mode == 4) {
        int wh = n0 / D;
        Bph = Wh + (size_t)wh * D * D;
        nb = n0 - wh * D; ldb = D;
    } else if (mode == 1) { Bph = Wh; nb = n0; ldb = FF; }
    else if (mode == 2) { Bph = Wh + (size_t)roi * RD * D; nb = n0; ldb = D; }
    else                { Bph = Wh; nb = n0; ldb = D; }

    if (mode == 2) Ah += (size_t)roi * BATCH * XPAD;

    float acc[2][4][4] = {};

    // ---- preload tile 0 ----
#pragma unroll
    for (int p = t; p < 1024; p += 256) {
        int row = p >> 3, c4 = (p & 7) * 4;
        *(uint2*)&AsH[row][c4] = *(const uint2*)(Ah + (size_t)(m0 + row) * lda + c4);
    }
#pragma unroll
    for (int p = t; p < 512; p += 256) {
        int k = p >> 4, n4 = (p & 15) * 4;
        uint2 zh = make_uint2(0u, 0u);
        if (k < K) zh = *(const uint2*)(Bph + (size_t)k * ldb + nb + n4);
        *(uint2*)&BsH[k][n4] = zh;
    }
    __syncthreads();

    for (int k0 = 0; k0 < K; k0 += 32) {
        bool has_next = (k0 + 32 < K);
        uint2 pa[4], pb[2];
        if (has_next) {
            int kn = k0 + 32;
#pragma unroll
            for (int i = 0; i < 4; ++i) {
                int p = t + i * 256;
                int row = p >> 3, c4 = (p & 7) * 4;
                pa[i] = *(const uint2*)(Ah + (size_t)(m0 + row) * lda + kn + c4);
            }
#pragma unroll
            for (int i = 0; i < 2; ++i) {
                int p = t + i * 256;
                int k = p >> 4, n4 = (p & 15) * 4;
                uint2 zh = make_uint2(0u, 0u);
                if (kn + k < K) zh = *(const uint2*)(Bph + (size_t)(kn + k) * ldb + nb + n4);
                pb[i] = zh;
            }
        }

#pragma unroll
        for (int ks = 0; ks < 2; ++ks) {
            int kb = ks * 16;
            unsigned aH[2][4];
            int aro = ((lane >> 3) & 1) * 8 + (lane & 7);
            int aco = kb + (lane >> 4) * 8;
#pragma unroll
            for (int mt = 0; mt < 2; ++mt) {
                int r = wm * 32 + mt * 16 + aro;
                ldsm_x4(smem_u32(&AsH[r][aco]), aH[mt][0], aH[mt][1], aH[mt][2], aH[mt][3]);
            }
            unsigned bH[4][2];
            int bro = kb + ((lane >> 3) & 1) * 8 + (lane & 7);
            int bco = wn * 32 + (lane >> 4) * 8;
#pragma unroll
            for (int np = 0; np < 2; ++np) {
                unsigned r0, r1, r2, r3;
                ldsm_x4t(smem_u32(&BsH[bro][bco + np * 16]), r0, r1, r2, r3);
                bH[np*2][0] = r0; bH[np*2][1] = r1; bH[np*2+1][0] = r2; bH[np*2+1][1] = r3;
            }
#pragma unroll
            for (int mt = 0; mt < 2; ++mt)
#pragma unroll
                for (int nt = 0; nt < 4; ++nt)
                    mma16816(acc[mt][nt], aH[mt], bH[nt]);
        }

        if (has_next) {
            __syncthreads();
#pragma unroll
            for (int i = 0; i < 4; ++i) {
                int p = t + i * 256;
                int row = p >> 3, c4 = (p & 7) * 4;
                *(uint2*)&AsH[row][c4] = pa[i];
            }
#pragma unroll
            for (int i = 0; i < 2; ++i) {
                int p = t + i * 256;
                int k = p >> 4, n4 = (p & 15) * 4;
                *(uint2*)&BsH[k][n4] = pb[i];
            }
            __syncthreads();
        }
    }

    // ---- epilogue ----
    int g = lane >> 2, tq = (lane & 3) * 2;
#pragma unroll
    for (int mt = 0; mt < 2; ++mt) {
        int r0 = m0 + wm * 32 + mt * 16 + g;
#pragma unroll
        for (int nt = 0; nt < 4; ++nt) {
            float* c = acc[mt][nt];
            if (mode == 0) {
                int wh = n0 / D;
                int colq = nb + wn * 32 + nt * 8 + tq;
                int hd = colq >> 5, dh = colq & 31;
                float2 bb = *(const float2*)(bias + wh * D + colq);
                float* o = (wh == 0) ? oq : ((wh == 1) ? ok : ov);
                int m = r0;
                int b = m / S, s = m - b * S;
                *(float2*)(o + (((size_t)b * NH + hd) * S + s) * DH + dh)
                    = make_float2(c[0] + bb.x, c[1] + bb.y);
                m = r0 + 8; b = m / S; s = m - b * S;
                *(float2*)(o + (((size_t)b * NH + hd) * S + s) * DH + dh)
                    = make_float2(c[2] + bb.x, c[3] + bb.y);
            } else if (mode == 4) {
                int wh = n0 / D;
                int colq = nb + wn * 32 + nt * 8 + tq;
                int hd = colq >> 5, dh = colq & 31;
                float2 bb = *(const float2*)(bias + wh * D + colq);
#pragma unroll
                for (int rr = 0; rr < 2; ++rr) {
                    int m = r0 + rr * 8;
                    int b = m / S, s = m - b * S;
                    int bhq = b * NH + hd;
                    float f0 = c[rr * 2 + 0] + bb.x;
                    float f1 = c[rr * 2 + 1] + bb.y;
                    if (wh == 0) {
                        f0 *= 0.17677669529663687f; f1 *= 0.17677669529663687f;
                        size_t off = ((size_t)bhq * S + s) * DH + dh;
                        *(unsigned*)(xqh + off)
                            = pack_hf2(__float2half(f0), __float2half(f1));
                    } else if (wh == 1) {
                        size_t off = ((size_t)bhq * DH + dh) * S + s;
                        xkh[off]     = __float2half(f0);
                        xkh[off + S] = __float2half(f1);
                    } else {
                        size_t off = ((size_t)bhq * S + s) * DH + dh;
                        *(unsigned*)(xvh + off)
                            = pack_hf2(__float2half(f0), __float2half(f1));
                    }
                }
            } else if (mode == 1) {
                int col = n0 + wn * 32 + nt * 8 + tq;
                float2 bb = *(const float2*)(bias + col);
                float f0 = gelu_exact(c[0] + bb.x), f1 = gelu_exact(c[1] + bb.y);
                *(unsigned*)(ofh + (size_t)r0 * FF + col)
                    = pack_hf2(__float2half(f0), __float2half(f1));
                f0 = gelu_exact(c[2] + bb.x); f1 = gelu_exact(c[3] + bb.y);
                *(unsigned*)(ofh + (size_t)(r0 + 8) * FF + col)
                    = pack_hf2(__float2half(f0), __float2half(f1));
            } else if (mode == 2) {
                int col = n0 + wn * 32 + nt * 8 + tq;
                float2 bb = *(const float2*)(bias + (size_t)roi * D + col);
                *(unsigned*)(ofh + ((size_t)r0 * S + roi) * D + col)
                    = pack_hf2(__float2half(c[0] + bb.x), __float2half(c[1] + bb.y));
                *(unsigned*)(ofh + ((size_t)(r0 + 8) * S + roi) * D + col)
                    = pack_hf2(__float2half(c[2] + bb.x), __float2half(c[3] + bb.y));
            } else {
                int col = n0 + wn * 32 + nt * 8 + tq;
                float2 bb = *(const float2*)(bias + col);
                *(unsigned*)(ofh + (size_t)r0 * D + col)
                    = pack_hf2(__float2half(c[0] + bb.x), __float2half(c[1] + bb.y));
                *(unsigned*)(ofh + (size_t)(r0 + 8) * D + col)
                    = pack_hf2(__float2half(c[2] + bb.x), __float2half(c[3] + bb.y));
            }
        }
    }
}

// ============================================================================
// Tensor-core attention: all single fp16; 1 MMA/k16; K/V register prefetch.
// ============================================================================
__global__ __launch_bounds__(256, 2) void attn_mma_kernel(
    const hf* __restrict__ qbh,
    const hf* __restrict__ kth, const hf* __restrict__ vbh,
    hf* __restrict__ oh)
{
    __shared__ hf Qh[208][40];
    __shared__ hf Kh[32][40];
    __shared__ hf Vh[32][40];

    int bh = blockIdx.x;
    int b = bh / NH, hd = bh - b * NH;
    int t = threadIdx.x, warp = t >> 5, lane = t & 31;
    int g = lane >> 2, tq = lane & 3;

    const hf* khb = kth + (size_t)bh * DH * S;
    const unsigned* vhp = (const unsigned*)(vbh + (size_t)bh * S * DH);
    const unsigned* qhp = (const unsigned*)(qbh + (size_t)bh * S * DH);

    for (int i = t; i < 208 * 16; i += 256) {
        int row = i >> 4, cp = i & 15;
        unsigned a = 0;
        if (row < S) a = qhp[row * 16 + cp];
        *(unsigned*)&Qh[row][cp * 2] = a;
    }
#pragma unroll
    for (int i = t; i < 512; i += 256) {
        int row = i >> 4, cp = i & 15;
        *(unsigned*)&Kh[row][cp * 2] = *(const unsigned*)(khb + row * S + cp * 2);
        *(unsigned*)&Vh[row][cp * 2] = vhp[row * 16 + cp];
    }
    __syncthreads();

    int nmt = (warp < 5) ? 2 : 1;
    int mt0 = warp * 16, mt1 = (8 + warp) * 16;
    int aro  = ((lane >> 3) & 1) * 8 + (lane & 7);
    int acoh = (lane >> 4) * 8;

    unsigned qH[2][2][4];
    for (int mi = 0; mi < nmt; ++mi) {
        int mrow = mi ? mt1 : mt0;
#pragma unroll
        for (int ks = 0; ks < 2; ++ks)
            ldsm_x4(smem_u32(&Qh[mrow + aro][ks * 16 + acoh]),
                    qH[mi][ks][0], qH[mi][ks][1], qH[mi][ks][2], qH[mi][ks][3]);
    }

    float oacc[2][4][4] = {};
    float lsum[2][2] = {};

    for (int kt = 0; kt < 7; ++kt) {
        bool has_next = (kt < 6);
        unsigned pk[2], pv[2];
        if (has_next) {
            int kn0 = (kt + 1) * 32;
#pragma unroll
            for (int i = 0; i < 2; ++i) {
                int p = t + i * 256;
                int row = p >> 4, cp = p & 15;
                int key = kn0 + cp * 2;
                unsigned a = 0;
                if (key < S) a = *(const unsigned*)(khb + row * S + key);
                pk[i] = a;
                int keyv = kn0 + row;
                unsigned av = 0;
                if (keyv < S) av = vhp[keyv * 16 + cp];
                pv[i] = av;
            }
        }

        int kt0 = kt * 32;
        for (int mi = 0; mi < nmt; ++mi) {
#pragma unroll
            for (int kg = 0; kg < 2; ++kg) {
                float sc2[2][4] = {};
#pragma unroll
                for (int ks = 0; ks < 2; ++ks) {
                    unsigned kh2[2][2], r0, r1, r2, r3;
                    ldsm_x4t(smem_u32(&Kh[ks * 16 + aro][kg * 16 + acoh]), r0, r1, r2, r3);
                    kh2[0][0] = r0; kh2[0][1] = r1; kh2[1][0] = r2; kh2[1][1] = r3;
#pragma unroll
                    for (int j = 0; j < 2; ++j)
                        mma16816(sc2[j], qH[mi][ks], kh2[j]);
                }
                float e[8];
#pragma unroll
                for (int j = 0; j < 2; ++j) {
                    int keyb = kt0 + (kg * 2 + j) * 8 + tq * 2;
                    float e0 = __expf(sc2[j][0]);
                    float e1 = __expf(sc2[j][1]);
                    float e2 = __expf(sc2[j][2]);
                    float e3 = __expf(sc2[j][3]);
                    if (keyb >= S)     { e0 = 0.f; e2 = 0.f; }
                    if (keyb + 1 >= S) { e1 = 0.f; e3 = 0.f; }
                    lsum[mi][0] += e0 + e1;
                    lsum[mi][1] += e2 + e3;
                    e[j * 4 + 0] = e0; e[j * 4 + 1] = e1;
                    e[j * 4 + 2] = e2; e[j * 4 + 3] = e3;
                }
                unsigned paH[4];
                paH[0] = pack_hf2(__float2half(e[0]), __float2half(e[1]));
                paH[1] = pack_hf2(__float2half(e[2]), __float2half(e[3]));
                paH[2] = pack_hf2(__float2half(e[4]), __float2half(e[5]));
                paH[3] = pack_hf2(__float2half(e[6]), __float2half(e[7]));
#pragma unroll
                for (int np = 0; np < 2; ++np) {
                    unsigned vh2[2][2], r0, r1, r2, r3;
                    ldsm_x4t(smem_u32(&Vh[kg * 16 + aro][np * 16 + acoh]), r0, r1, r2, r3);
                    vh2[0][0] = r0; vh2[0][1] = r1; vh2[1][0] = r2; vh2[1][1] = r3;
#pragma unroll
                    for (int j = 0; j < 2; ++j)
                        mma16816(oacc[mi][np * 2 + j], paH, vh2[j]);
                }
            }
        }

        if (has_next) {
            __syncthreads();
#pragma unroll
            for (int i = 0; i < 2; ++i) {
                int p = t + i * 256;
                int row = p >> 4, cp = p & 15;
                *(unsigned*)&Kh[row][cp * 2] = pk[i];
                *(unsigned*)&Vh[row][cp * 2] = pv[i];
            }
            __syncthreads();
        }
    }

    for (int mi = 0; mi < nmt; ++mi) {
        float l0 = lsum[mi][0], l1 = lsum[mi][1];
        l0 += __shfl_xor_sync(0xffffffffu, l0, 1);
        l0 += __shfl_xor_sync(0xffffffffu, l0, 2);
        l1 += __shfl_xor_sync(0xffffffffu, l1, 1);
        l1 += __shfl_xor_sync(0xffffffffu, l1, 2);
        float i0 = 1.f / l0, i1 = 1.f / l1;
        int mrow = mi ? mt1 : mt0;
        int s0 = mrow + g;
#pragma unroll
        for (int n8 = 0; n8 < 4; ++n8) {
            int col = hd * DH + n8 * 8 + tq * 2;
            if (s0 < S) {
                float u0 = oacc[mi][n8][0] * i0, u1 = oacc[mi][n8][1] * i0;
                size_t off = ((size_t)b * S + s0) * D + col;
                *(unsigned*)(oh + off) = pack_hf2(__float2half(u0), __float2half(u1));
            }
            if (s0 + 8 < S) {
                float u0 = oacc[mi][n8][2] * i1, u1 = oacc[mi][n8][3] * i1;
                size_t off = ((size_t)b * S + s0 + 8) * D + col;
                *(unsigned*)(oh + off) = pack_hf2(__float2half(u0), __float2half(u1));
            }
        }
    }
}

// ============================================================================
// add + LayerNorm: hh = LN(raw16 + hh)   (residual stream fully fp16)
// ============================================================================
__global__ void addln_kernel(const hf* __restrict__ raw,
                             const float* __restrict__ lng,
                             const float* __restrict__ lnb,
                             hf* __restrict__ hh)
{
    int row = blockIdx.x * 8 + (threadIdx.x >> 5);
    int lane = threadIdx.x & 31;
    float vv[6];
    float sum = 0.f, sq = 0.f;
#pragma unroll
    for (int j = 0; j < 6; ++j) {
        int c = lane + 32 * j;
        vv[j] = __half2float(raw[(size_t)row * D + c])
              + __half2float(hh[(size_t)row * D + c]);
        sum += vv[j]; sq += vv[j] * vv[j];
    }
#pragma unroll
    for (int o = 16; o > 0; o >>= 1) {
        sum += __shfl_xor_sync(0xffffffffu, sum, o);
        sq  += __shfl_xor_sync(0xffffffffu, sq,  o);
    }
    float mean = sum * (1.f / D);
    float rstd = rsqrtf(sq * (1.f / D) - mean * mean + 1e-5f);
#pragma unroll
    for (int j = 0; j < 6; ++j) {
        int c = lane + 32 * j;
        float val = (vv[j] - mean) * rstd * lng[c] + lnb[c];
        hh[(size_t)row * D + c] = __float2half(val);
    }
}

// ============================================================================
// token epilogue: hh = gelu(LN(raw16)) + pos   (per-roi params)
// ============================================================================
__global__ void tok_finish_kernel(const hf* __restrict__ raw,
                                  const float* __restrict__ lng,
                                  const float* __restrict__ lnb,
                                  const float* __restrict__ pos,
                                  hf* __restrict__ hh)
{
    int row = blockIdx.x * 8 + (threadIdx.x >> 5);
    int roi = row % S;
    int lane = threadIdx.x & 31;
    float vv[6];
    float sum = 0.f, sq = 0.f;
#pragma unroll
    for (int j = 0; j < 6; ++j) {
        vv[j] = __half2float(raw[(size_t)row * D + lane + 32 * j]);
        sum += vv[j]; sq += vv[j] * vv[j];
    }
#pragma unroll
    for (int o = 16; o > 0; o >>= 1) {
        sum += __shfl_xor_sync(0xffffffffu, sum, o);
        sq  += __shfl_xor_sync(0xffffffffu, sq,  o);
    }
    float mean = sum * (1.f / D);
    float rstd = rsqrtf(sq * (1.f / D) - mean * mean + 1e-5f);
#pragma unroll
    for (int j = 0; j < 6; ++j) {
        int c = lane + 32 * j;
        float v = (vv[j] - mean) * rstd * lng[(size_t)roi * D + c] + lnb[(size_t)roi * D + c];
        float val = gelu_exact(v) + pos[(size_t)roi * D + c];
        hh[(size_t)row * D + c] = __float2half(val);
    }
}

// ---------------- pooled attention (Q=1 via linearity) ---------------------
__global__ void pool_attn_kernel(const float* __restrict__ q,
                                 const float* __restrict__ k,
                                 const float* __restrict__ v,
                                 float* __restrict__ out)
{
    __shared__ float qm[DH];
    __shared__ float sc[S];
    __shared__ float red[2];
    int bh = blockIdx.x;
    int b = bh / NH, hd = bh % NH;
    size_t base = (size_t)bh * S * DH;
    int t = threadIdx.x;
    if (t < DH) {
        float s = 0.f;
        for (int j = 0; j < S; ++j) s += q[base + j * DH + t];
        qm[t] = s * (1.f / S) * 0.17677669529663687f;
    }
    __syncthreads();
    if (t < S) {
        float x = 0.f;
#pragma unroll
        for (int i = 0; i < DH; ++i) x += qm[i] * k[base + t * DH + i];
        sc[t] = x;
    }
    __syncthreads();
    if (t == 0) {
        float mx = -1e30f;
        for (int s = 0; s < S; ++s) mx = fmaxf(mx, sc[s]);
        red[0] = mx;
    }
    __syncthreads();
    if (t < S) sc[t] = __expf(sc[t] - red[0]);
    __syncthreads();
    if (t == 0) {
        float l = 0.f;
        for (int s = 0; s < S; ++s) l += sc[s];
        red[1] = 1.f / l;
    }
    __syncthreads();
    if (t < DH) {
        float o = 0.f;
        for (int s = 0; s < S; ++s) o += sc[s] * v[base + s * DH + t];
        out[(size_t)b * D + hd * DH + t] = o * red[1];
    }
}

// ---------------- pooled projection ----------------------------------------
__global__ void pool_proj_kernel(const float* __restrict__ in,
                                 const float* __restrict__ W,
                                 const float* __restrict__ bias,
                                 float* __restrict__ out)
{
    __shared__ float row[D];
    int b = blockIdx.x, d = threadIdx.x;
    row[d] = in[(size_t)b * D + d];
    __syncthreads();
    float s = bias[d];
    for (int k = 0; k < D; ++k) s += row[k] * W[(size_t)k * D + d];
    out[(size_t)b * D + d] = s;
}

// ---------------- classifier head ------------------------------------------
__global__ void cls_kernel(const float* __restrict__ in,
                           const float* __restrict__ g,  const float* __restrict__ bt,
                           const float* __restrict__ W1, const float* __restrict__ b1,
                           const float* __restrict__ W2, const float* __restrict__ b2,
                           const float* __restrict__ W3, const float* __restrict__ b3,
                           float* __restrict__ out)
{
    __shared__ float z[D];
    __shared__ float z1[96];
    __shared__ float z2[48];
    __shared__ float red[2];
    int b = blockIdx.x, t = threadIdx.x;
    float v = in[(size_t)b * D + t];
    z[t] = v;
    __syncthreads();
    if (t == 0) {
        float s = 0.f, sq = 0.f;
        for (int i = 0; i < D; ++i) { s += z[i]; sq += z[i] * z[i]; }
        float m = s / D;
        red[0] = m;
        red[1] = rsqrtf(sq / D - m * m + 1e-5f);
    }
    __syncthreads();
    z[t] = (v - red[0]) * red[1] * g[t] + bt[t];
    __syncthreads();
    if (t < 96) {
        float a = b1[t];
        for (int k = 0; k < D; ++k) a += z[k] * W1[k * 96 + t];
        z1[t] = gelu_exact(a);
    }
    __syncthreads();
    if (t < 48) {
        float a = b2[t];
        for (int k = 0; k < 96; ++k) a += z1[k] * W2[k * 48 + t];
        z2[t] = gelu_exact(a);
    }
    __syncthreads();
    if (t < 2) {
        float a = b3[t];
        for (int k = 0; k < 48; ++k) a += z2[k] * W3[k * 2 + t];
        out[(size_t)b * 2 + t] = a;
    }
}

// ---------------- launch ----------------------------------------------------
extern "C" void kernel_launch(void* const* d_in, const int* in_sizes, int n_in,
                              void* d_out, int out_size)
{
    const float* x        = (const float*)d_in[0];
    const float* roi_W    = (const float*)d_in[1];
    const float* roi_b    = (const float*)d_in[2];
    const float* roi_lng  = (const float*)d_in[3];
    const float* roi_lnb  = (const float*)d_in[4];
    const float* pos_emb  = (const float*)d_in[5];
    const float* enc_Wqkv = (const float*)d_in[6];
    const float* enc_bqkv = (const float*)d_in[7];
    const float* enc_Wo   = (const float*)d_in[8];
    const float* enc_bo   = (const float*)d_in[9];
    const float* enc_ln1g = (const float*)d_in[10];
    const float* enc_ln1b = (const float*)d_in[11];
    const float* enc_W1   = (const float*)d_in[12];
    const float* enc_b1   = (const float*)d_in[13];
    const float* enc_W2   = (const float*)d_in[14];
    const float* enc_b2   = (const float*)d_in[15];
    const float* enc_ln2g = (const float*)d_in[16];
    const float* enc_ln2b = (const float*)d_in[17];
    const float* pool_Wqkv= (const float*)d_in[18];
    const float* pool_bqkv= (const float*)d_in[19];
    const float* pool_Wo  = (const float*)d_in[20];
    const float* pool_bo  = (const float*)d_in[21];
    const float* cls_lng  = (const float*)d_in[22];
    const float* cls_lnb  = (const float*)d_in[23];
    const float* cls_W1   = (const float*)d_in[24];
    const float* cls_b1   = (const float*)d_in[25];
    const float* cls_W2   = (const float*)d_in[26];
    const float* cls_b2   = (const float*)d_in[27];
    const float* cls_W3   = (const float*)d_in[28];
    const float* cls_b3   = (const float*)d_in[29];
    float* out = (float*)d_out;

    float *q, *k, *v, *pool, *pooled;
    hf *xh, *raw16, *hh, *ah, *fh;
    hf *qbh, *kth, *vbh;
    hf *rwh, *qkvh, *woh, *w1h, *w2h, *pwh;
    cudaGetSymbolAddress((void**)&q,    g_q);
    cudaGetSymbolAddress((void**)&k,    g_k);
    cudaGetSymbolAddress((void**)&v,    g_v);
    cudaGetSymbolAddress((void**)&pool, g_pool);
    cudaGetSymbolAddress((void**)&pooled, g_pooled);
    cudaGetSymbolAddress((void**)&xh, g_xh);
    cudaGetSymbolAddress((void**)&raw16, g_raw16);
    cudaGetSymbolAddress((void**)&hh, g_hh);
    cudaGetSymbolAddress((void**)&ah, g_ah);
    cudaGetSymbolAddress((void**)&fh, g_fh);
    cudaGetSymbolAddress((void**)&qbh, g_qbh);
    cudaGetSymbolAddress((void**)&kth, g_kth);
    cudaGetSymbolAddress((void**)&vbh, g_vbh);
    cudaGetSymbolAddress((void**)&rwh, g_rwh);
    cudaGetSymbolAddress((void**)&qkvh, g_qkvh);
    cudaGetSymbolAddress((void**)&woh, g_woh);
    cudaGetSymbolAddress((void**)&w1h, g_w1h);
    cudaGetSymbolAddress((void**)&w2h, g_w2h);
    cudaGetSymbolAddress((void**)&pwh, g_pwh);

    // ---- pre-convert weights & x (single fp16) ----
    cvt_x_kernel<<<(200 * BATCH * XPAD + 255) / 256, 256>>>(x, xh);
    cvt1_kernel<<<(200 * RD * D + 255) / 256, 256>>>(roi_W, rwh, 200 * RD * D);
    cvt1_kernel<<<(NL * 3 * D * D + 255) / 256, 256>>>(enc_Wqkv, qkvh, NL * 3 * D * D);
    cvt1_kernel<<<(NL * D * D + 255) / 256, 256>>>(enc_Wo, woh, NL * D * D);
    cvt1_kernel<<<(NL * D * FF + 255) / 256, 256>>>(enc_W1, w1h, NL * D * FF);
    cvt1_kernel<<<(NL * FF * D + 255) / 256, 256>>>(enc_W2, w2h, NL * FF * D);
    cvt1_kernel<<<(3 * D * D + 255) / 256, 256>>>(pool_Wqkv, pwh, 3 * D * D);

    // ---- tokenizer ----
    mma_gemm_kernel<<<dim3(2, 3, 200), 256>>>(xh, rwh, roi_b,
        nullptr, nullptr, nullptr, raw16,
        nullptr, nullptr, nullptr, 2, RD, XPAD);
    tok_finish_kernel<<<MTOT / 8, 256>>>(raw16, roi_lng, roi_lnb, pos_emb, hh);

    // ---- encoder layers ----
    for (int l = 0; l < NL; ++l) {
        mma_gemm_kernel<<<dim3(MTOT / 128, 9, 1), 256>>>(hh,
            qkvh + (size_t)l * 3 * D * D, enc_bqkv + (size_t)l * 3 * D,
            nullptr, nullptr, nullptr, nullptr,
            qbh, kth, vbh, 4, D, D);
        attn_mma_kernel<<<BATCH * NH, 256>>>(qbh, kth, vbh, ah);
        mma_gemm_kernel<<<dim3(MTOT / 128, 3, 1), 256>>>(ah,
            woh + (size_t)l * D * D, enc_bo + l * D,
            nullptr, nullptr, nullptr, raw16,
            nullptr, nullptr, nullptr, 3, D, D);
        addln_kernel<<<MTOT / 8, 256>>>(raw16, enc_ln1g + l * D, enc_ln1b + l * D, hh);
        mma_gemm_kernel<<<dim3(MTOT / 128, 9, 1), 256>>>(hh,
            w1h + (size_t)l * D * FF, enc_b1 + l * FF,
            nullptr, nullptr, nullptr, fh,
            nullptr, nullptr, nullptr, 1, D, D);
        mma_gemm_kernel<<<dim3(MTOT / 128, 3, 1), 256>>>(fh,
            w2h + (size_t)l * FF * D, enc_b2 + l * D,
            nullptr, nullptr, nullptr, raw16,
            nullptr, nullptr, nullptr, 3, FF, FF);
        addln_kernel<<<MTOT / 8, 256>>>(raw16, enc_ln2g + l * D, enc_ln2b + l * D, hh);
    }

    // ---- pooling (fp32 QKV path) ----
    mma_gemm_kernel<<<dim3(MTOT / 128, 9, 1), 256>>>(hh, pwh, pool_bqkv,
        q, k, v, nullptr,
        nullptr, nullptr, nullptr, 0, D, D);
    pool_attn_kernel<<<BATCH * NH, 256>>>(q, k, v, pool);
    pool_proj_kernel<<<BATCH, 192>>>(pool, pool_Wo, pool_bo, pooled);

    // ---- classifier ----
    cls_kernel<<<BATCH, 192>>>(pooled, cls_lng, cls_lnb, cls_W1, cls_b1,
                               cls_W2, cls_b2, cls_W3, cls_b3, out);
}